// round 6
// baseline (speedup 1.0000x reference)
#include <cuda_runtime.h>
#include <cuda_bf16.h>
#include <cstdint>

#define NN 100000
#define NE 3200000
#define HD 128
#define HD2 256
#define NL 4
#define NG 512
#define SCAN_NB 98   // ceil(100000/1024)

// ---------------- PTX helpers (all plain-sm_103 legal) -------------------------
__device__ __forceinline__ uint32_t smem_u32(const void* p) {
    uint32_t a;
    asm("{ .reg .u64 t; cvta.to.shared.u64 t, %1; cvt.u32.u64 %0, t; }" : "=r"(a) : "l"(p));
    return a;
}
#define LDSM4(r, a) \
    asm volatile("ldmatrix.sync.aligned.m8n8.x4.shared.b16 {%0,%1,%2,%3}, [%4];" \
        : "=r"((r)[0]), "=r"((r)[1]), "=r"((r)[2]), "=r"((r)[3]) : "r"(a))
#define MMA16816(d, a, b0, b1) \
    asm volatile("mma.sync.aligned.m16n8k16.row.col.f32.bf16.bf16.f32 " \
        "{%0,%1,%2,%3}, {%4,%5,%6,%7}, {%8,%9}, {%0,%1,%2,%3};" \
        : "+f"((d)[0]), "+f"((d)[1]), "+f"((d)[2]), "+f"((d)[3]) \
        : "r"((a)[0]), "r"((a)[1]), "r"((a)[2]), "r"((a)[3]), "r"(b0), "r"(b1))
#define CP_ASYNC16(s, g, sz) \
    asm volatile("cp.async.cg.shared.global [%0], [%1], 16, %2;" :: "r"(s), "l"(g), "r"(sz))
#define CP_COMMIT() asm volatile("cp.async.commit_group;")
#define CP_WAIT0()  asm volatile("cp.async.wait_group 0;")

// ---------------- device scratch ----------------------------------------------
__device__ __align__(16) float          g_h[NN * HD];            // fp32 node features
__device__ __align__(16) __nv_bfloat16  g_zhi[NN * HD];
__device__ __align__(16) __nv_bfloat16  g_zlo[NN * HD];
__device__ __align__(16) __nv_bfloat16  g_uhi[(size_t)NN * HD2];
__device__ __align__(16) __nv_bfloat16  g_ulo[(size_t)NN * HD2];
__device__ __align__(16) __nv_bfloat16  g_B1w[NL * 2 * HD2 * HD];   // [l][hi|lo][n=256][k=128]
__device__ __align__(16) __nv_bfloat16  g_B2w[NL * 2 * HD * HD2];   // [l][hi|lo][n=128][k=256]
__device__ int g_deg[NN], g_inc[NN], g_rowptr[NN + 1], g_cursor[NN], g_col[NE];
__device__ int g_bsum[SCAN_NB], g_boff[SCAN_NB];

// ---------------- CSR build ---------------------------------------------------
__global__ void k_zero_deg() {
    int i = blockIdx.x * blockDim.x + threadIdx.x;
    if (i < NN) g_deg[i] = 0;
}
__global__ void k_hist(const int* __restrict__ ei) {
    int e = blockIdx.x * blockDim.x + threadIdx.x;
    if (e < NE) atomicAdd(&g_deg[ei[NE + e]], 1);
}
__global__ void k_scan1() {
    __shared__ int s[1024];
    int tid = threadIdx.x, i = blockIdx.x * 1024 + tid;
    int v = (i < NN) ? g_deg[i] : 0;
    s[tid] = v; __syncthreads();
    for (int off = 1; off < 1024; off <<= 1) {
        int t = (tid >= off) ? s[tid - off] : 0;
        __syncthreads(); s[tid] += t; __syncthreads();
    }
    if (i < NN) g_inc[i] = s[tid];
    if (tid == 1023) g_bsum[blockIdx.x] = s[1023];
}
__global__ void k_scan2() {
    __shared__ int s[128];
    int tid = threadIdx.x;
    int v = (tid < SCAN_NB) ? g_bsum[tid] : 0;
    s[tid] = v; __syncthreads();
    for (int off = 1; off < 128; off <<= 1) {
        int t = (tid >= off) ? s[tid - off] : 0;
        __syncthreads(); s[tid] += t; __syncthreads();
    }
    if (tid < SCAN_NB) g_boff[tid] = s[tid] - v;
}
__global__ void k_finalize() {
    int i = blockIdx.x * blockDim.x + threadIdx.x;
    if (i >= NN) return;
    int ex = g_inc[i] - g_deg[i] + g_boff[i >> 10];
    g_rowptr[i] = ex; g_cursor[i] = ex;
    if (i == NN - 1) g_rowptr[NN] = ex + g_deg[i];
}
__global__ void k_scatter(const int* __restrict__ ei) {
    int e = blockIdx.x * blockDim.x + threadIdx.x;
    if (e < NE) {
        int p = atomicAdd(&g_cursor[ei[NE + e]], 1);
        g_col[p] = ei[e];
    }
}

// ---------------- weight packing: [n][k] row-major bf16 hi/lo ------------------
__global__ void k_packW1(const float* __restrict__ W1) {
    int idx = blockIdx.x * blockDim.x + threadIdx.x;     // NL*256*128
    if (idx >= NL * HD2 * HD) return;
    int l = idx / (HD2 * HD), rem = idx % (HD2 * HD);
    int n = rem / HD, k = rem % HD;
    float w = W1[((size_t)l * HD + k) * HD2 + n];
    __nv_bfloat16 h = __float2bfloat16(w);
    __nv_bfloat16 lo = __float2bfloat16(w - __bfloat162float(h));
    size_t base = (size_t)l * 2 * HD2 * HD;
    g_B1w[base + (size_t)n * HD + k] = h;
    g_B1w[base + (size_t)HD2 * HD + (size_t)n * HD + k] = lo;
}
__global__ void k_packW2(const float* __restrict__ W2) {
    int idx = blockIdx.x * blockDim.x + threadIdx.x;     // NL*128*256
    if (idx >= NL * HD * HD2) return;
    int l = idx / (HD * HD2), rem = idx % (HD * HD2);
    int n = rem / HD2, k = rem % HD2;
    float w = W2[((size_t)l * HD2 + k) * HD + n];
    __nv_bfloat16 h = __float2bfloat16(w);
    __nv_bfloat16 lo = __float2bfloat16(w - __bfloat162float(h));
    size_t base = (size_t)l * 2 * HD * HD2;
    g_B2w[base + (size_t)n * HD2 + k] = h;
    g_B2w[base + (size_t)HD * HD2 + (size_t)n * HD2 + k] = lo;
}

// ---------------- atom embedding ------------------------------------------------
__global__ void k_embed(const float* __restrict__ x, const float* __restrict__ W,
                        const float* __restrict__ b) {
    int idx = blockIdx.x * blockDim.x + threadIdx.x;
    if (idx >= NN * HD) return;
    int n = idx >> 7, c = idx & 127;
    const float* xr = x + n * 9;
    float acc = b[c];
#pragma unroll
    for (int k = 0; k < 9; k++) acc = fmaf(xr[k], W[k * HD + c], acc);
    g_h[idx] = acc;
}

// ---------------- GIN aggregation -> z (bf16 hi/lo) ---------------------------
__global__ void k_agg(const float* __restrict__ eps, int l) {
    int wid = (blockIdx.x * blockDim.x + threadIdx.x) >> 5;
    if (wid >= NN) return;
    int lane = threadIdx.x & 31;
    const float4* h4 = (const float4*)g_h;
    float sc = 1.0f + eps[l];
    float4 a = h4[wid * 32 + lane];
    a.x *= sc; a.y *= sc; a.z *= sc; a.w *= sc;
    int j = g_rowptr[wid], e = g_rowptr[wid + 1];
    for (; j + 3 < e; j += 4) {
        int m0 = g_col[j], m1 = g_col[j + 1], m2 = g_col[j + 2], m3 = g_col[j + 3];
        float4 v0 = h4[m0 * 32 + lane], v1 = h4[m1 * 32 + lane];
        float4 v2 = h4[m2 * 32 + lane], v3 = h4[m3 * 32 + lane];
        a.x += v0.x + v1.x + v2.x + v3.x;
        a.y += v0.y + v1.y + v2.y + v3.y;
        a.z += v0.z + v1.z + v2.z + v3.z;
        a.w += v0.w + v1.w + v2.w + v3.w;
    }
    for (; j < e; j++) {
        float4 v = h4[g_col[j] * 32 + lane];
        a.x += v.x; a.y += v.y; a.z += v.z; a.w += v.w;
    }
    float vv[4] = {a.x, a.y, a.z, a.w};
    uint32_t hw[2], lw[2];
#pragma unroll
    for (int p = 0; p < 2; p++) {
        __nv_bfloat16 h0 = __float2bfloat16(vv[2 * p]);
        __nv_bfloat16 h1 = __float2bfloat16(vv[2 * p + 1]);
        __nv_bfloat16 l0 = __float2bfloat16(vv[2 * p] - __bfloat162float(h0));
        __nv_bfloat16 l1 = __float2bfloat16(vv[2 * p + 1] - __bfloat162float(h1));
        hw[p] = (uint32_t)__bfloat16_as_ushort(h0) | ((uint32_t)__bfloat16_as_ushort(h1) << 16);
        lw[p] = (uint32_t)__bfloat16_as_ushort(l0) | ((uint32_t)__bfloat16_as_ushort(l1) << 16);
    }
    // streaming stores: keep h resident in L2
    __stcs((uint2*)(g_zhi + (size_t)wid * HD) + lane, make_uint2(hw[0], hw[1]));
    __stcs((uint2*)(g_zlo + (size_t)wid * HD) + lane, make_uint2(lw[0], lw[1]));
}

// ---------------- HMMA GEMM + BN + ReLU (bf16x3 emulation) ---------------------
// MODE 0: u = relu(BN(z @ W1)), KDIM=128, NOUT=256, out bf16 hi/lo (streaming)
// MODE 1: h = relu(BN(u @ W2)), KDIM=256, NOUT=128, out fp32 (L2-resident)
// Persistent CTAs, 512 threads (16 warps, 4x4 warp grid), tile 128 rows x NOUT.
// A staged per 128-k chunk via cp.async.cg; B (hi/lo, full K) smem-resident.
template <int KDIM, int NOUT, int MODE>
__global__ void __launch_bounds__(512, 1)
k_gemm_mma(int l, const float* __restrict__ bb, const float* __restrict__ gm,
           const float* __restrict__ bt, const float* __restrict__ mn,
           const float* __restrict__ vr) {
    constexpr int PC  = 128 * 2 + 16;    // A chunk pitch (bytes)
    constexpr int PB  = KDIM * 2 + 16;   // B row pitch (bytes)
    constexpr int KT  = KDIM / 128;      // A k-chunks
    constexpr int NT  = NOUT / 32;       // n8-tiles per warp
    constexpr int NW  = NOUT / 4;        // warp n-width
    constexpr int RCB = KDIM / 8;        // uint4 per B row
    constexpr int AHI = 0;
    constexpr int ALO = 128 * PC;
    constexpr int BHI = 2 * 128 * PC;
    constexpr int BLO = BHI + NOUT * PB;
    constexpr int SAC = BLO + NOUT * PB;
    constexpr int SCC = SAC + NOUT * 4;

    extern __shared__ char smem[];
    const uint32_t sb = smem_u32(smem);
    const int tid = threadIdx.x, wid = tid >> 5, lane = tid & 31;
    const int wm = wid & 3, wn = wid >> 2;

    const __nv_bfloat16* in_hi = (MODE == 0) ? g_zhi : g_uhi;
    const __nv_bfloat16* in_lo = (MODE == 0) ? g_zlo : g_ulo;
    const __nv_bfloat16* Bsrc = (MODE == 0)
        ? (g_B1w + (size_t)l * 2 * HD2 * HD)
        : (g_B2w + (size_t)l * 2 * HD * HD2);

    // ---- B (hi|lo) via cp.async, BN constants ---------------------------------
    for (int c = tid; c < 2 * NOUT * RCB; c += 512) {
        int buf = c / (NOUT * RCB);
        int rem = c - buf * NOUT * RCB;
        int n = rem / RCB, q = rem % RCB;
        const void* g = Bsrc + (size_t)c * 8;
        uint32_t s = sb + (buf ? BLO : BHI) + n * PB + q * 16;
        CP_ASYNC16(s, g, 16);
    }
    for (int c = tid; c < NOUT; c += 512) {
        float a = gm[c] * rsqrtf(vr[c] + 1e-5f);
        ((float*)(smem + SAC))[c] = a;
        ((float*)(smem + SCC))[c] = fmaf(a, bb[c] - mn[c], bt[c]);
    }
    CP_COMMIT();
    CP_WAIT0();
    __syncthreads();

    const float* Ac = (const float*)(smem + SAC);
    const float* Cc = (const float*)(smem + SCC);
    const uint32_t lrow = (lane & 15), lcol = (lane >> 4) * 16;
    const int tiles = (NN + 127) / 128;

    for (int tile = blockIdx.x; tile < tiles; tile += gridDim.x) {
        const int row0 = tile * 128;

        float acc[2][NT][4];
#pragma unroll
        for (int i = 0; i < 2; i++)
#pragma unroll
            for (int j = 0; j < NT; j++)
#pragma unroll
                for (int q = 0; q < 4; q++) acc[i][j][q] = 0.f;

#pragma unroll
        for (int kt = 0; kt < KT; kt++) {
            if (kt > 0) __syncthreads();          // all warps done with prev chunk
            // ---- stage A chunk [128 rows x 128k] hi/lo ------------------------
            for (int c = tid; c < 4096; c += 512) {
                int buf = c >> 11, rem = c & 2047, r = rem >> 4, q = rem & 15;
                int row = row0 + r;
                int ok = (row < NN);
                const __nv_bfloat16* src = buf ? in_lo : in_hi;
                const void* g = src + (size_t)(ok ? row : 0) * KDIM + kt * 128 + q * 8;
                uint32_t s = sb + (buf ? ALO : AHI) + r * PC + q * 16;
                CP_ASYNC16(s, g, ok ? 16 : 0);
            }
            CP_COMMIT();
            CP_WAIT0();
            __syncthreads();

#pragma unroll
            for (int ks = 0; ks < 8; ks++) {
                uint32_t ah[2][4], al[2][4];
#pragma unroll
                for (int i = 0; i < 2; i++) {
                    uint32_t aAddr = sb + AHI + (wm * 32 + i * 16 + lrow) * PC + ks * 32 + lcol;
                    LDSM4(ah[i], aAddr);
                    LDSM4(al[i], aAddr + (ALO - AHI));
                }
#pragma unroll
                for (int np = 0; np < NT / 2; np++) {
                    int n0 = wn * NW + np * 16;
                    uint32_t bAddr = sb + BHI + (n0 + lrow) * PB + (kt * 8 + ks) * 32 + lcol;
                    uint32_t bh[4], bl[4];
                    LDSM4(bh, bAddr);
                    LDSM4(bl, bAddr + (BLO - BHI));
#pragma unroll
                    for (int i = 0; i < 2; i++) {
                        MMA16816(acc[i][2 * np],     ah[i], bh[0], bh[2]);
                        MMA16816(acc[i][2 * np],     ah[i], bl[0], bl[2]);
                        MMA16816(acc[i][2 * np],     al[i], bh[0], bh[2]);
                        MMA16816(acc[i][2 * np + 1], ah[i], bh[1], bh[3]);
                        MMA16816(acc[i][2 * np + 1], ah[i], bl[1], bl[3]);
                        MMA16816(acc[i][2 * np + 1], al[i], bh[1], bh[3]);
                    }
                }
            }
        }

        // ---- epilogue: BN + ReLU ------------------------------------------------
#pragma unroll
        for (int i = 0; i < 2; i++) {
#pragma unroll
            for (int j = 0; j < NT; j++) {
                int r0 = row0 + wm * 32 + i * 16 + (lane >> 2);
                int r1 = r0 + 8;
                int c = wn * NW + j * 8 + (lane & 3) * 2;
                float a0 = Ac[c], a1 = Ac[c + 1], c0 = Cc[c], c1 = Cc[c + 1];
                float y00 = fmaxf(fmaf(acc[i][j][0], a0, c0), 0.f);
                float y01 = fmaxf(fmaf(acc[i][j][1], a1, c1), 0.f);
                float y10 = fmaxf(fmaf(acc[i][j][2], a0, c0), 0.f);
                float y11 = fmaxf(fmaf(acc[i][j][3], a1, c1), 0.f);
                if (MODE == 0) {
                    if (r0 < NN) {
                        __nv_bfloat16 h0 = __float2bfloat16(y00), h1 = __float2bfloat16(y01);
                        uint32_t hw = (uint32_t)__bfloat16_as_ushort(h0) | ((uint32_t)__bfloat16_as_ushort(h1) << 16);
                        __nv_bfloat16 l0 = __float2bfloat16(y00 - __bfloat162float(h0));
                        __nv_bfloat16 l1 = __float2bfloat16(y01 - __bfloat162float(h1));
                        uint32_t lw = (uint32_t)__bfloat16_as_ushort(l0) | ((uint32_t)__bfloat16_as_ushort(l1) << 16);
                        __stcs((uint32_t*)(g_uhi + (size_t)r0 * HD2 + c), hw);
                        __stcs((uint32_t*)(g_ulo + (size_t)r0 * HD2 + c), lw);
                    }
                    if (r1 < NN) {
                        __nv_bfloat16 h0 = __float2bfloat16(y10), h1 = __float2bfloat16(y11);
                        uint32_t hw = (uint32_t)__bfloat16_as_ushort(h0) | ((uint32_t)__bfloat16_as_ushort(h1) << 16);
                        __nv_bfloat16 l0 = __float2bfloat16(y10 - __bfloat162float(h0));
                        __nv_bfloat16 l1 = __float2bfloat16(y11 - __bfloat162float(h1));
                        uint32_t lw = (uint32_t)__bfloat16_as_ushort(l0) | ((uint32_t)__bfloat16_as_ushort(l1) << 16);
                        __stcs((uint32_t*)(g_uhi + (size_t)r1 * HD2 + c), hw);
                        __stcs((uint32_t*)(g_ulo + (size_t)r1 * HD2 + c), lw);
                    }
                } else {
                    if (r0 < NN) *(float2*)(g_h + (size_t)r0 * HD + c) = make_float2(y00, y01);
                    if (r1 < NN) *(float2*)(g_h + (size_t)r1 * HD + c) = make_float2(y10, y11);
                }
            }
        }
        __syncthreads();
    }
}

// ---------------- global mean pool --------------------------------------------
__global__ void k_pool(const int* __restrict__ batch, float* __restrict__ out) {
    int g = blockIdx.x, c = threadIdx.x;
    int lo = 0, hi = NN;
    while (lo < hi) { int mid = (lo + hi) >> 1; if (batch[mid] < g) lo = mid + 1; else hi = mid; }
    int start = lo;
    lo = start; hi = NN;
    while (lo < hi) { int mid = (lo + hi) >> 1; if (batch[mid] < g + 1) lo = mid + 1; else hi = mid; }
    int end = lo;
    float acc = 0.f;
    int n = start;
    for (; n + 3 < end; n += 4) {
        acc += g_h[(n + 0) * HD + c];
        acc += g_h[(n + 1) * HD + c];
        acc += g_h[(n + 2) * HD + c];
        acc += g_h[(n + 3) * HD + c];
    }
    for (; n < end; n++) acc += g_h[n * HD + c];
    float cnt = (float)(end - start);
    out[g * HD + c] = acc / fmaxf(cnt, 1.f);
}

// ---------------- launch --------------------------------------------------------
extern "C" void kernel_launch(void* const* d_in, const int* in_sizes, int n_in,
                              void* d_out, int out_size) {
    const float* x    = (const float*)d_in[0];
    const int*   ei   = (const int*)d_in[1];
    const int*   bat  = (const int*)d_in[2];
    const float* Wemb = (const float*)d_in[3];
    const float* bemb = (const float*)d_in[4];
    const float* eps  = (const float*)d_in[5];
    const float* W1   = (const float*)d_in[6];
    const float* b1   = (const float*)d_in[7];
    const float* g1   = (const float*)d_in[8];
    const float* be1  = (const float*)d_in[9];
    const float* m1   = (const float*)d_in[10];
    const float* v1   = (const float*)d_in[11];
    const float* W2   = (const float*)d_in[12];
    const float* b2   = (const float*)d_in[13];
    const float* g2   = (const float*)d_in[14];
    const float* be2  = (const float*)d_in[15];
    const float* m2   = (const float*)d_in[16];
    const float* v2   = (const float*)d_in[17];
    float* out = (float*)d_out;

    // smem: MODE0 = 210944 B, MODE1 = 205824 B
    cudaFuncSetAttribute(k_gemm_mma<128, 256, 0>, cudaFuncAttributeMaxDynamicSharedMemorySize, 210944);
    cudaFuncSetAttribute(k_gemm_mma<256, 128, 1>, cudaFuncAttributeMaxDynamicSharedMemorySize, 205824);

    // CSR build + weight packing (once per launch)
    k_zero_deg<<<(NN + 255) / 256, 256>>>();
    k_hist<<<(NE + 255) / 256, 256>>>(ei);
    k_scan1<<<SCAN_NB, 1024>>>();
    k_scan2<<<1, 128>>>();
    k_finalize<<<(NN + 255) / 256, 256>>>();
    k_scatter<<<(NE + 255) / 256, 256>>>(ei);
    k_packW1<<<(NL * HD2 * HD + 255) / 256, 256>>>(W1);
    k_packW2<<<(NL * HD * HD2 + 255) / 256, 256>>>(W2);

    k_embed<<<(NN * HD + 255) / 256, 256>>>(x, Wemb, bemb);

    for (int l = 0; l < NL; l++) {
        k_agg<<<(NN + 7) / 8, 256>>>(eps, l);
        k_gemm_mma<128, 256, 0><<<148, 512, 210944>>>(l, b1 + l * HD2, g1 + l * HD2,
                                                      be1 + l * HD2, m1 + l * HD2, v1 + l * HD2);
        k_gemm_mma<256, 128, 1><<<148, 512, 205824>>>(l, b2 + l * HD, g2 + l * HD,
                                                      be2 + l * HD, m2 + l * HD, v2 + l * HD);
    }

    k_pool<<<NG, 128>>>(bat, out);
}

// round 7
// speedup vs baseline: 1.0143x; 1.0143x over previous
#include <cuda_runtime.h>
#include <cuda_bf16.h>
#include <cuda_fp16.h>
#include <cstdint>

#define NN 100000
#define NE 3200000
#define HD 128
#define HD2 256
#define NL 4
#define NG 512
#define CSRB 148
#define CSRT 256
#define CHUNK 676   // ceil(NN/148)
#define CPT 3       // ceil(CHUNK/CSRT)

// ---------------- PTX helpers (all plain-sm_103 legal) -------------------------
__device__ __forceinline__ uint32_t smem_u32(const void* p) {
    uint32_t a;
    asm("{ .reg .u64 t; cvta.to.shared.u64 t, %1; cvt.u32.u64 %0, t; }" : "=r"(a) : "l"(p));
    return a;
}
#define LDSM4(r, a) \
    asm volatile("ldmatrix.sync.aligned.m8n8.x4.shared.b16 {%0,%1,%2,%3}, [%4];" \
        : "=r"((r)[0]), "=r"((r)[1]), "=r"((r)[2]), "=r"((r)[3]) : "r"(a))
#define MMA16816(d, a, b0, b1) \
    asm volatile("mma.sync.aligned.m16n8k16.row.col.f32.bf16.bf16.f32 " \
        "{%0,%1,%2,%3}, {%4,%5,%6,%7}, {%8,%9}, {%0,%1,%2,%3};" \
        : "+f"((d)[0]), "+f"((d)[1]), "+f"((d)[2]), "+f"((d)[3]) \
        : "r"((a)[0]), "r"((a)[1]), "r"((a)[2]), "r"((a)[3]), "r"(b0), "r"(b1))
#define CP_ASYNC16(s, g, sz) \
    asm volatile("cp.async.cg.shared.global [%0], [%1], 16, %2;" :: "r"(s), "l"(g), "r"(sz))
#define CP_COMMIT() asm volatile("cp.async.commit_group;")
#define CP_WAIT0()  asm volatile("cp.async.wait_group 0;")

// ---------------- device scratch ----------------------------------------------
__device__ __align__(16) float          g_h[NN * HD];            // fp32 node features
__device__ __align__(16) __half         g_h16[NN * HD];          // fp16 copy (gather)
__device__ __align__(16) __nv_bfloat16  g_zhi[NN * HD];
__device__ __align__(16) __nv_bfloat16  g_zlo[NN * HD];
__device__ __align__(16) __nv_bfloat16  g_uhi[(size_t)NN * HD2];
__device__ __align__(16) __nv_bfloat16  g_ulo[(size_t)NN * HD2];
__device__ __align__(16) __nv_bfloat16  g_B1w[NL * 2 * HD2 * HD];   // [l][hi|lo][n=256][k=128]
__device__ __align__(16) __nv_bfloat16  g_B2w[NL * 2 * HD * HD2];   // [l][hi|lo][n=128][k=256]
__device__ int g_deg[NN], g_rowptr[NN + 1], g_cursor[NN], g_col[NE];
__device__ int g_part[CSRB], g_poff[CSRB];
__device__ volatile int g_bar;                                      // reset by k_pool

// ---------------- grid-wide barrier (148 resident CTAs) ------------------------
__device__ __forceinline__ void gridbar(int phase) {
    __syncthreads();
    if (threadIdx.x == 0) {
        __threadfence();
        atomicAdd((int*)&g_bar, 1);
        while (g_bar < CSRB * phase) { }
        __threadfence();
    }
    __syncthreads();
}

// ---------------- fused CSR build (one launch) ----------------------------------
__global__ void __launch_bounds__(CSRT, 1) k_csr(const int* __restrict__ ei) {
    const int tid = threadIdx.x, bid = blockIdx.x;
    const int gstride = CSRB * CSRT;
    const int gtid = bid * CSRT + tid;
    __shared__ int s[CSRT];

    // A: zero degrees
    for (int i = gtid; i < NN; i += gstride) g_deg[i] = 0;
    gridbar(1);
    // B: histogram
    for (int e = gtid; e < NE; e += gstride) atomicAdd(&g_deg[ei[NE + e]], 1);
    gridbar(2);
    // C: per-thread contiguous sums + block scan
    const int start = bid * CHUNK;
    const int end = (start + CHUNK < NN) ? start + CHUNK : NN;
    const int t0 = start + tid * CPT;
    int own = 0;
#pragma unroll
    for (int q = 0; q < CPT; q++) {
        int i = t0 + q;
        if (i < end) own += g_deg[i];
    }
    s[tid] = own;
    __syncthreads();
    for (int off = 1; off < CSRT; off <<= 1) {
        int t = (tid >= off) ? s[tid - off] : 0;
        __syncthreads(); s[tid] += t; __syncthreads();
    }
    const int texcl = s[tid] - own;
    if (tid == CSRT - 1) g_part[bid] = s[tid];
    gridbar(3);
    // D: scan CTA partials (serial, 148 adds)
    if (bid == 0 && tid == 0) {
        int r = 0;
        for (int b = 0; b < CSRB; b++) { g_poff[b] = r; r += g_part[b]; }
    }
    gridbar(4);
    // E: write rowptr + cursor
    int run = g_poff[bid] + texcl;
#pragma unroll
    for (int q = 0; q < CPT; q++) {
        int i = t0 + q;
        if (i < end) { g_rowptr[i] = run; g_cursor[i] = run; run += g_deg[i]; }
    }
    if (gtid == 0) g_rowptr[NN] = NE;
    gridbar(5);
    // F: scatter edge sources
    for (int e = gtid; e < NE; e += gstride) {
        int p = atomicAdd(&g_cursor[ei[NE + e]], 1);
        g_col[p] = ei[e];
    }
}

// ---------------- weight packing: [n][k] row-major bf16 hi/lo ------------------
__global__ void k_packW1(const float* __restrict__ W1) {
    int idx = blockIdx.x * blockDim.x + threadIdx.x;     // NL*256*128
    if (idx >= NL * HD2 * HD) return;
    int l = idx / (HD2 * HD), rem = idx % (HD2 * HD);
    int n = rem / HD, k = rem % HD;
    float w = W1[((size_t)l * HD + k) * HD2 + n];
    __nv_bfloat16 h = __float2bfloat16(w);
    __nv_bfloat16 lo = __float2bfloat16(w - __bfloat162float(h));
    size_t base = (size_t)l * 2 * HD2 * HD;
    g_B1w[base + (size_t)n * HD + k] = h;
    g_B1w[base + (size_t)HD2 * HD + (size_t)n * HD + k] = lo;
}
__global__ void k_packW2(const float* __restrict__ W2) {
    int idx = blockIdx.x * blockDim.x + threadIdx.x;     // NL*128*256
    if (idx >= NL * HD * HD2) return;
    int l = idx / (HD * HD2), rem = idx % (HD * HD2);
    int n = rem / HD2, k = rem % HD2;
    float w = W2[((size_t)l * HD2 + k) * HD + n];
    __nv_bfloat16 h = __float2bfloat16(w);
    __nv_bfloat16 lo = __float2bfloat16(w - __bfloat162float(h));
    size_t base = (size_t)l * 2 * HD * HD2;
    g_B2w[base + (size_t)n * HD2 + k] = h;
    g_B2w[base + (size_t)HD * HD2 + (size_t)n * HD2 + k] = lo;
}

// ---------------- atom embedding ------------------------------------------------
__global__ void k_embed(const float* __restrict__ x, const float* __restrict__ W,
                        const float* __restrict__ b) {
    int idx = blockIdx.x * blockDim.x + threadIdx.x;
    if (idx >= NN * HD) return;
    int n = idx >> 7, c = idx & 127;
    const float* xr = x + n * 9;
    float acc = b[c];
#pragma unroll
    for (int k = 0; k < 9; k++) acc = fmaf(xr[k], W[k * HD + c], acc);
    g_h[idx] = acc;
    g_h16[idx] = __float2half(acc);
}

// ---------------- GIN aggregation -> z (bf16 hi/lo) ---------------------------
// l==0: fp32 neighbor gather (signed pre-ReLU values). l>0: fp16 gather (half traffic).
__global__ void k_agg(const float* __restrict__ eps, int l) {
    int node = (blockIdx.x * blockDim.x + threadIdx.x) >> 5;
    if (node >= NN) return;
    int lane = threadIdx.x & 31;
    const float4* h4 = (const float4*)g_h;
    float sc = 1.0f + eps[l];
    float4 self = h4[node * 32 + lane];
    float ax = self.x * sc, ay = self.y * sc, az = self.z * sc, aw = self.w * sc;
    int j = g_rowptr[node], e = g_rowptr[node + 1];
    if (l == 0) {
        for (; j + 3 < e; j += 4) {
            int m0 = g_col[j], m1 = g_col[j + 1], m2 = g_col[j + 2], m3 = g_col[j + 3];
            float4 v0 = h4[m0 * 32 + lane], v1 = h4[m1 * 32 + lane];
            float4 v2 = h4[m2 * 32 + lane], v3 = h4[m3 * 32 + lane];
            ax += v0.x + v1.x + v2.x + v3.x;
            ay += v0.y + v1.y + v2.y + v3.y;
            az += v0.z + v1.z + v2.z + v3.z;
            aw += v0.w + v1.w + v2.w + v3.w;
        }
        for (; j < e; j++) {
            float4 v = h4[g_col[j] * 32 + lane];
            ax += v.x; ay += v.y; az += v.z; aw += v.w;
        }
    } else {
        const uint2* h16 = (const uint2*)g_h16;   // row = 32 uint2 (4 halves each)
        for (; j + 3 < e; j += 4) {
            uint2 v0 = h16[(size_t)g_col[j]     * 32 + lane];
            uint2 v1 = h16[(size_t)g_col[j + 1] * 32 + lane];
            uint2 v2 = h16[(size_t)g_col[j + 2] * 32 + lane];
            uint2 v3 = h16[(size_t)g_col[j + 3] * 32 + lane];
            float2 f;
            f = __half22float2(*(__half2*)&v0.x); ax += f.x; ay += f.y;
            f = __half22float2(*(__half2*)&v0.y); az += f.x; aw += f.y;
            f = __half22float2(*(__half2*)&v1.x); ax += f.x; ay += f.y;
            f = __half22float2(*(__half2*)&v1.y); az += f.x; aw += f.y;
            f = __half22float2(*(__half2*)&v2.x); ax += f.x; ay += f.y;
            f = __half22float2(*(__half2*)&v2.y); az += f.x; aw += f.y;
            f = __half22float2(*(__half2*)&v3.x); ax += f.x; ay += f.y;
            f = __half22float2(*(__half2*)&v3.y); az += f.x; aw += f.y;
        }
        for (; j < e; j++) {
            uint2 v = h16[(size_t)g_col[j] * 32 + lane];
            float2 f;
            f = __half22float2(*(__half2*)&v.x); ax += f.x; ay += f.y;
            f = __half22float2(*(__half2*)&v.y); az += f.x; aw += f.y;
        }
    }
    float vv[4] = {ax, ay, az, aw};
    uint32_t hw[2], lw[2];
#pragma unroll
    for (int p = 0; p < 2; p++) {
        __nv_bfloat16 h0 = __float2bfloat16(vv[2 * p]);
        __nv_bfloat16 h1 = __float2bfloat16(vv[2 * p + 1]);
        __nv_bfloat16 l0 = __float2bfloat16(vv[2 * p] - __bfloat162float(h0));
        __nv_bfloat16 l1 = __float2bfloat16(vv[2 * p + 1] - __bfloat162float(h1));
        hw[p] = (uint32_t)__bfloat16_as_ushort(h0) | ((uint32_t)__bfloat16_as_ushort(h1) << 16);
        lw[p] = (uint32_t)__bfloat16_as_ushort(l0) | ((uint32_t)__bfloat16_as_ushort(l1) << 16);
    }
    __stcs((uint2*)(g_zhi + (size_t)node * HD) + lane, make_uint2(hw[0], hw[1]));
    __stcs((uint2*)(g_zlo + (size_t)node * HD) + lane, make_uint2(lw[0], lw[1]));
}

// ---------------- HMMA GEMM + BN + ReLU (bf16x3 emulation) ---------------------
// MODE 0: u = relu(BN(z @ W1)), KDIM=128, NOUT=256, out bf16 hi/lo (streaming)
// MODE 1: h = relu(BN(u @ W2)), KDIM=256, NOUT=128, out fp32 + fp16
template <int KDIM, int NOUT, int MODE>
__global__ void __launch_bounds__(512, 1)
k_gemm_mma(int l, const float* __restrict__ bb, const float* __restrict__ gm,
           const float* __restrict__ bt, const float* __restrict__ mn,
           const float* __restrict__ vr) {
    constexpr int PC  = 128 * 2 + 16;    // A chunk pitch (bytes)
    constexpr int PB  = KDIM * 2 + 16;   // B row pitch (bytes)
    constexpr int KT  = KDIM / 128;      // A k-chunks
    constexpr int NT  = NOUT / 32;       // n8-tiles per warp
    constexpr int NW  = NOUT / 4;        // warp n-width
    constexpr int RCB = KDIM / 8;        // uint4 per B row
    constexpr int AHI = 0;
    constexpr int ALO = 128 * PC;
    constexpr int BHI = 2 * 128 * PC;
    constexpr int BLO = BHI + NOUT * PB;
    constexpr int SAC = BLO + NOUT * PB;
    constexpr int SCC = SAC + NOUT * 4;

    extern __shared__ char smem[];
    const uint32_t sb = smem_u32(smem);
    const int tid = threadIdx.x, wid = tid >> 5, lane = tid & 31;
    const int wm = wid & 3, wn = wid >> 2;

    const __nv_bfloat16* in_hi = (MODE == 0) ? g_zhi : g_uhi;
    const __nv_bfloat16* in_lo = (MODE == 0) ? g_zlo : g_ulo;
    const __nv_bfloat16* Bsrc = (MODE == 0)
        ? (g_B1w + (size_t)l * 2 * HD2 * HD)
        : (g_B2w + (size_t)l * 2 * HD * HD2);

    for (int c = tid; c < 2 * NOUT * RCB; c += 512) {
        int buf = c / (NOUT * RCB);
        int rem = c - buf * NOUT * RCB;
        int n = rem / RCB, q = rem % RCB;
        const void* g = Bsrc + (size_t)c * 8;
        uint32_t s = sb + (buf ? BLO : BHI) + n * PB + q * 16;
        CP_ASYNC16(s, g, 16);
    }
    for (int c = tid; c < NOUT; c += 512) {
        float a = gm[c] * rsqrtf(vr[c] + 1e-5f);
        ((float*)(smem + SAC))[c] = a;
        ((float*)(smem + SCC))[c] = fmaf(a, bb[c] - mn[c], bt[c]);
    }
    CP_COMMIT();
    CP_WAIT0();
    __syncthreads();

    const float* Ac = (const float*)(smem + SAC);
    const float* Cc = (const float*)(smem + SCC);
    const uint32_t lrow = (lane & 15), lcol = (lane >> 4) * 16;
    const int tiles = (NN + 127) / 128;

    for (int tile = blockIdx.x; tile < tiles; tile += gridDim.x) {
        const int row0 = tile * 128;

        float acc[2][NT][4];
#pragma unroll
        for (int i = 0; i < 2; i++)
#pragma unroll
            for (int j = 0; j < NT; j++)
#pragma unroll
                for (int q = 0; q < 4; q++) acc[i][j][q] = 0.f;

#pragma unroll
        for (int kt = 0; kt < KT; kt++) {
            if (kt > 0) __syncthreads();
            for (int c = tid; c < 4096; c += 512) {
                int buf = c >> 11, rem = c & 2047, r = rem >> 4, q = rem & 15;
                int row = row0 + r;
                int ok = (row < NN);
                const __nv_bfloat16* src = buf ? in_lo : in_hi;
                const void* g = src + (size_t)(ok ? row : 0) * KDIM + kt * 128 + q * 8;
                uint32_t s = sb + (buf ? ALO : AHI) + r * PC + q * 16;
                CP_ASYNC16(s, g, ok ? 16 : 0);
            }
            CP_COMMIT();
            CP_WAIT0();
            __syncthreads();

#pragma unroll
            for (int ks = 0; ks < 8; ks++) {
                uint32_t ah[2][4], al[2][4];
#pragma unroll
                for (int i = 0; i < 2; i++) {
                    uint32_t aAddr = sb + AHI + (wm * 32 + i * 16 + lrow) * PC + ks * 32 + lcol;
                    LDSM4(ah[i], aAddr);
                    LDSM4(al[i], aAddr + (ALO - AHI));
                }
#pragma unroll
                for (int np = 0; np < NT / 2; np++) {
                    int n0 = wn * NW + np * 16;
                    uint32_t bAddr = sb + BHI + (n0 + lrow) * PB + (kt * 8 + ks) * 32 + lcol;
                    uint32_t bh[4], bl[4];
                    LDSM4(bh, bAddr);
                    LDSM4(bl, bAddr + (BLO - BHI));
#pragma unroll
                    for (int i = 0; i < 2; i++) {
                        MMA16816(acc[i][2 * np],     ah[i], bh[0], bh[2]);
                        MMA16816(acc[i][2 * np],     ah[i], bl[0], bl[2]);
                        MMA16816(acc[i][2 * np],     al[i], bh[0], bh[2]);
                        MMA16816(acc[i][2 * np + 1], ah[i], bh[1], bh[3]);
                        MMA16816(acc[i][2 * np + 1], ah[i], bl[1], bl[3]);
                        MMA16816(acc[i][2 * np + 1], al[i], bh[1], bh[3]);
                    }
                }
            }
        }

#pragma unroll
        for (int i = 0; i < 2; i++) {
#pragma unroll
            for (int j = 0; j < NT; j++) {
                int r0 = row0 + wm * 32 + i * 16 + (lane >> 2);
                int r1 = r0 + 8;
                int c = wn * NW + j * 8 + (lane & 3) * 2;
                float a0 = Ac[c], a1 = Ac[c + 1], c0 = Cc[c], c1 = Cc[c + 1];
                float y00 = fmaxf(fmaf(acc[i][j][0], a0, c0), 0.f);
                float y01 = fmaxf(fmaf(acc[i][j][1], a1, c1), 0.f);
                float y10 = fmaxf(fmaf(acc[i][j][2], a0, c0), 0.f);
                float y11 = fmaxf(fmaf(acc[i][j][3], a1, c1), 0.f);
                if (MODE == 0) {
                    if (r0 < NN) {
                        __nv_bfloat16 h0 = __float2bfloat16(y00), h1 = __float2bfloat16(y01);
                        uint32_t hw = (uint32_t)__bfloat16_as_ushort(h0) | ((uint32_t)__bfloat16_as_ushort(h1) << 16);
                        __nv_bfloat16 l0 = __float2bfloat16(y00 - __bfloat162float(h0));
                        __nv_bfloat16 l1 = __float2bfloat16(y01 - __bfloat162float(h1));
                        uint32_t lw = (uint32_t)__bfloat16_as_ushort(l0) | ((uint32_t)__bfloat16_as_ushort(l1) << 16);
                        __stcs((uint32_t*)(g_uhi + (size_t)r0 * HD2 + c), hw);
                        __stcs((uint32_t*)(g_ulo + (size_t)r0 * HD2 + c), lw);
                    }
                    if (r1 < NN) {
                        __nv_bfloat16 h0 = __float2bfloat16(y10), h1 = __float2bfloat16(y11);
                        uint32_t hw = (uint32_t)__bfloat16_as_ushort(h0) | ((uint32_t)__bfloat16_as_ushort(h1) << 16);
                        __nv_bfloat16 l0 = __float2bfloat16(y10 - __bfloat162float(h0));
                        __nv_bfloat16 l1 = __float2bfloat16(y11 - __bfloat162float(h1));
                        uint32_t lw = (uint32_t)__bfloat16_as_ushort(l0) | ((uint32_t)__bfloat16_as_ushort(l1) << 16);
                        __stcs((uint32_t*)(g_uhi + (size_t)r1 * HD2 + c), hw);
                        __stcs((uint32_t*)(g_ulo + (size_t)r1 * HD2 + c), lw);
                    }
                } else {
                    if (r0 < NN) {
                        *(float2*)(g_h + (size_t)r0 * HD + c) = make_float2(y00, y01);
                        *(__half2*)(g_h16 + (size_t)r0 * HD + c) = __floats2half2_rn(y00, y01);
                    }
                    if (r1 < NN) {
                        *(float2*)(g_h + (size_t)r1 * HD + c) = make_float2(y10, y11);
                        *(__half2*)(g_h16 + (size_t)r1 * HD + c) = __floats2half2_rn(y10, y11);
                    }
                }
            }
        }
        __syncthreads();
    }
}

// ---------------- global mean pool (+ barrier reset for next replay) ----------
__global__ void k_pool(const int* __restrict__ batch, float* __restrict__ out) {
    if (blockIdx.x == 0 && threadIdx.x == 0) g_bar = 0;
    int g = blockIdx.x, c = threadIdx.x;
    int lo = 0, hi = NN;
    while (lo < hi) { int mid = (lo + hi) >> 1; if (batch[mid] < g) lo = mid + 1; else hi = mid; }
    int start = lo;
    lo = start; hi = NN;
    while (lo < hi) { int mid = (lo + hi) >> 1; if (batch[mid] < g + 1) lo = mid + 1; else hi = mid; }
    int end = lo;
    float acc = 0.f;
    int n = start;
    for (; n + 3 < end; n += 4) {
        acc += g_h[(n + 0) * HD + c];
        acc += g_h[(n + 1) * HD + c];
        acc += g_h[(n + 2) * HD + c];
        acc += g_h[(n + 3) * HD + c];
    }
    for (; n < end; n++) acc += g_h[n * HD + c];
    float cnt = (float)(end - start);
    out[g * HD + c] = acc / fmaxf(cnt, 1.f);
}

// ---------------- launch --------------------------------------------------------
extern "C" void kernel_launch(void* const* d_in, const int* in_sizes, int n_in,
                              void* d_out, int out_size) {
    const float* x    = (const float*)d_in[0];
    const int*   ei   = (const int*)d_in[1];
    const int*   bat  = (const int*)d_in[2];
    const float* Wemb = (const float*)d_in[3];
    const float* bemb = (const float*)d_in[4];
    const float* eps  = (const float*)d_in[5];
    const float* W1   = (const float*)d_in[6];
    const float* b1   = (const float*)d_in[7];
    const float* g1   = (const float*)d_in[8];
    const float* be1  = (const float*)d_in[9];
    const float* m1   = (const float*)d_in[10];
    const float* v1   = (const float*)d_in[11];
    const float* W2   = (const float*)d_in[12];
    const float* b2   = (const float*)d_in[13];
    const float* g2   = (const float*)d_in[14];
    const float* be2  = (const float*)d_in[15];
    const float* m2   = (const float*)d_in[16];
    const float* v2   = (const float*)d_in[17];
    float* out = (float*)d_out;

    // smem: MODE0 = 210944 B, MODE1 = 205824 B
    cudaFuncSetAttribute(k_gemm_mma<128, 256, 0>, cudaFuncAttributeMaxDynamicSharedMemorySize, 210944);
    cudaFuncSetAttribute(k_gemm_mma<256, 128, 1>, cudaFuncAttributeMaxDynamicSharedMemorySize, 205824);

    k_embed<<<(NN * HD + 255) / 256, 256>>>(x, Wemb, bemb);
    k_packW1<<<(NL * HD2 * HD + 255) / 256, 256>>>(W1);
    k_packW2<<<(NL * HD * HD2 + 255) / 256, 256>>>(W2);
    k_csr<<<CSRB, CSRT>>>(ei);

    for (int l = 0; l < NL; l++) {
        k_agg<<<(NN + 7) / 8, 256>>>(eps, l);
        k_gemm_mma<128, 256, 0><<<148, 512, 210944>>>(l, b1 + l * HD2, g1 + l * HD2,
                                                      be1 + l * HD2, m1 + l * HD2, v1 + l * HD2);
        k_gemm_mma<256, 128, 1><<<148, 512, 205824>>>(l, b2 + l * HD, g2 + l * HD,
                                                      be2 + l * HD, m2 + l * HD, v2 + l * HD);
    }

    k_pool<<<NG, 128>>>(bat, out);
}

// round 8
// speedup vs baseline: 1.4853x; 1.4644x over previous
#include <cuda_runtime.h>
#include <cuda_fp16.h>
#include <cstdint>

#define NN 100000
#define NE 3200000
#define HD 128
#define HD2 256
#define NL 4
#define NG 512
#define CSRB 148
#define CSRT 512
#define CHUNK 676   // ceil(NN/148)
#define CPT 2       // ceil(CHUNK/CSRT)

// ---------------- PTX helpers (all plain-sm_103 legal) -------------------------
__device__ __forceinline__ uint32_t smem_u32(const void* p) {
    uint32_t a;
    asm("{ .reg .u64 t; cvta.to.shared.u64 t, %1; cvt.u32.u64 %0, t; }" : "=r"(a) : "l"(p));
    return a;
}
#define LDSM4(r, a) \
    asm volatile("ldmatrix.sync.aligned.m8n8.x4.shared.b16 {%0,%1,%2,%3}, [%4];" \
        : "=r"((r)[0]), "=r"((r)[1]), "=r"((r)[2]), "=r"((r)[3]) : "r"(a))
#define MMA16816H(d, a, b0, b1) \
    asm volatile("mma.sync.aligned.m16n8k16.row.col.f32.f16.f16.f32 " \
        "{%0,%1,%2,%3}, {%4,%5,%6,%7}, {%8,%9}, {%0,%1,%2,%3};" \
        : "+f"((d)[0]), "+f"((d)[1]), "+f"((d)[2]), "+f"((d)[3]) \
        : "r"((a)[0]), "r"((a)[1]), "r"((a)[2]), "r"((a)[3]), "r"(b0), "r"(b1))
#define CP_ASYNC16(s, g, sz) \
    asm volatile("cp.async.cg.shared.global [%0], [%1], 16, %2;" :: "r"(s), "l"(g), "r"(sz))
#define CP_COMMIT() asm volatile("cp.async.commit_group;")
#define CP_WAIT0()  asm volatile("cp.async.wait_group 0;")

// ---------------- device scratch ----------------------------------------------
__device__ __align__(16) float   g_h[NN * HD];               // fp32 h (last layer only, for pool)
__device__ __align__(16) __half  g_h16[NN * HD];             // fp16 h (agg input)
__device__ __align__(16) __half  g_z16[NN * HD];             // fp16 z (GEMM1 A)
__device__ __align__(16) __half  g_u16[(size_t)NN * HD2];    // fp16 u (GEMM2 A)
__device__ __align__(16) __half  g_B1h[NL * 2 * HD2 * HD];   // [l][hi|lo][n=256][k=128]
__device__ __align__(16) __half  g_B2h[NL * 2 * HD * HD2];   // [l][hi|lo][n=128][k=256]
__device__ int g_deg[NN], g_rowptr[NN + 1], g_cursor[NN], g_col[NE];
__device__ int g_part[CSRB], g_poff[CSRB];
__device__ volatile int g_bar;                               // reset by k_pool

// ---------------- grid-wide barrier (148 resident CTAs) ------------------------
__device__ __forceinline__ void gridbar(int phase) {
    __syncthreads();
    if (threadIdx.x == 0) {
        __threadfence();
        atomicAdd((int*)&g_bar, 1);
        while (g_bar < CSRB * phase) { }
        __threadfence();
    }
    __syncthreads();
}

// ---------------- fused CSR build (one launch, 512 thr) ------------------------
__global__ void __launch_bounds__(CSRT, 1) k_csr(const int* __restrict__ ei) {
    const int tid = threadIdx.x, bid = blockIdx.x;
    const int gstride = CSRB * CSRT;
    const int gtid = bid * CSRT + tid;
    __shared__ int s[CSRT];

    for (int i = gtid; i < NN; i += gstride) g_deg[i] = 0;
    gridbar(1);
    for (int e = gtid; e < NE; e += gstride) atomicAdd(&g_deg[ei[NE + e]], 1);
    gridbar(2);
    const int start = bid * CHUNK;
    const int end = (start + CHUNK < NN) ? start + CHUNK : NN;
    const int t0 = start + tid * CPT;
    int own = 0;
#pragma unroll
    for (int q = 0; q < CPT; q++) {
        int i = t0 + q;
        if (i < end) own += g_deg[i];
    }
    s[tid] = own;
    __syncthreads();
    for (int off = 1; off < CSRT; off <<= 1) {
        int t = (tid >= off) ? s[tid - off] : 0;
        __syncthreads(); s[tid] += t; __syncthreads();
    }
    const int texcl = s[tid] - own;
    if (tid == CSRT - 1) g_part[bid] = s[tid];
    gridbar(3);
    if (bid == 0 && tid == 0) {
        int r = 0;
        for (int b = 0; b < CSRB; b++) { g_poff[b] = r; r += g_part[b]; }
    }
    gridbar(4);
    int run = g_poff[bid] + texcl;
#pragma unroll
    for (int q = 0; q < CPT; q++) {
        int i = t0 + q;
        if (i < end) { g_rowptr[i] = run; g_cursor[i] = run; run += g_deg[i]; }
    }
    if (gtid == 0) g_rowptr[NN] = NE;
    gridbar(5);
    for (int e = gtid; e < NE; e += gstride) {
        int p = atomicAdd(&g_cursor[ei[NE + e]], 1);
        g_col[p] = ei[e];
    }
}

// ---------------- weight packing: [n][k] row-major fp16 hi/lo ------------------
__global__ void k_packW1(const float* __restrict__ W1) {
    int idx = blockIdx.x * blockDim.x + threadIdx.x;     // NL*256*128
    if (idx >= NL * HD2 * HD) return;
    int l = idx / (HD2 * HD), rem = idx % (HD2 * HD);
    int n = rem / HD, k = rem % HD;
    float w = W1[((size_t)l * HD + k) * HD2 + n];
    __half h = __float2half(w);
    __half lo = __float2half(w - __half2float(h));
    size_t base = (size_t)l * 2 * HD2 * HD;
    g_B1h[base + (size_t)n * HD + k] = h;
    g_B1h[base + (size_t)HD2 * HD + (size_t)n * HD + k] = lo;
}
__global__ void k_packW2(const float* __restrict__ W2) {
    int idx = blockIdx.x * blockDim.x + threadIdx.x;     // NL*128*256
    if (idx >= NL * HD * HD2) return;
    int l = idx / (HD * HD2), rem = idx % (HD * HD2);
    int n = rem / HD2, k = rem % HD2;
    float w = W2[((size_t)l * HD2 + k) * HD + n];
    __half h = __float2half(w);
    __half lo = __float2half(w - __half2float(h));
    size_t base = (size_t)l * 2 * HD * HD2;
    g_B2h[base + (size_t)n * HD2 + k] = h;
    g_B2h[base + (size_t)HD * HD2 + (size_t)n * HD2 + k] = lo;
}

// ---------------- atom embedding (h16 only) -------------------------------------
__global__ void k_embed(const float* __restrict__ x, const float* __restrict__ W,
                        const float* __restrict__ b) {
    int idx = blockIdx.x * blockDim.x + threadIdx.x;
    if (idx >= NN * HD) return;
    int n = idx >> 7, c = idx & 127;
    const float* xr = x + n * 9;
    float acc = b[c];
#pragma unroll
    for (int k = 0; k < 9; k++) acc = fmaf(xr[k], W[k * HD + c], acc);
    g_h16[idx] = __float2half(acc);
}

// ---------------- GIN aggregation: z16 = fp16((1+eps)*h + sum nbr h) ------------
__global__ void k_agg(const float* __restrict__ eps, int l) {
    int node = (blockIdx.x * blockDim.x + threadIdx.x) >> 5;
    if (node >= NN) return;
    int lane = threadIdx.x & 31;
    const uint2* h16 = (const uint2*)g_h16;   // row = 32 uint2 (4 halves each)
    float sc = 1.0f + eps[l];
    uint2 sv = h16[(size_t)node * 32 + lane];
    float2 f0 = __half22float2(*(__half2*)&sv.x);
    float2 f1 = __half22float2(*(__half2*)&sv.y);
    float ax = f0.x * sc, ay = f0.y * sc, az = f1.x * sc, aw = f1.y * sc;
    int j = g_rowptr[node], e = g_rowptr[node + 1];
    for (; j + 3 < e; j += 4) {
        uint2 v0 = h16[(size_t)g_col[j]     * 32 + lane];
        uint2 v1 = h16[(size_t)g_col[j + 1] * 32 + lane];
        uint2 v2 = h16[(size_t)g_col[j + 2] * 32 + lane];
        uint2 v3 = h16[(size_t)g_col[j + 3] * 32 + lane];
        float2 f;
        f = __half22float2(*(__half2*)&v0.x); ax += f.x; ay += f.y;
        f = __half22float2(*(__half2*)&v0.y); az += f.x; aw += f.y;
        f = __half22float2(*(__half2*)&v1.x); ax += f.x; ay += f.y;
        f = __half22float2(*(__half2*)&v1.y); az += f.x; aw += f.y;
        f = __half22float2(*(__half2*)&v2.x); ax += f.x; ay += f.y;
        f = __half22float2(*(__half2*)&v2.y); az += f.x; aw += f.y;
        f = __half22float2(*(__half2*)&v3.x); ax += f.x; ay += f.y;
        f = __half22float2(*(__half2*)&v3.y); az += f.x; aw += f.y;
    }
    for (; j < e; j++) {
        uint2 v = h16[(size_t)g_col[j] * 32 + lane];
        float2 f;
        f = __half22float2(*(__half2*)&v.x); ax += f.x; ay += f.y;
        f = __half22float2(*(__half2*)&v.y); az += f.x; aw += f.y;
    }
    __half2 p0 = __floats2half2_rn(ax, ay);
    __half2 p1 = __floats2half2_rn(az, aw);
    uint2 ov = make_uint2(*(uint32_t*)&p0, *(uint32_t*)&p1);
    __stcs((uint2*)(g_z16 + (size_t)node * HD) + lane, ov);
}

// ---------------- HMMA GEMM + BN + ReLU (fp16 A x fp16 hi/lo B, 2 terms) --------
// MODE 0: u16 = relu(BN(z @ W1)), KDIM=128, NOUT=256
// MODE 1: h16 (+h fp32 if last) = relu(BN(u @ W2)), KDIM=256, NOUT=128
template <int KDIM, int NOUT, int MODE>
__global__ void __launch_bounds__(512, 1)
k_gemm_mma(int l, int last, const float* __restrict__ bb, const float* __restrict__ gm,
           const float* __restrict__ bt, const float* __restrict__ mn,
           const float* __restrict__ vr) {
    constexpr int PC  = 128 * 2 + 16;    // A chunk pitch (bytes)
    constexpr int PB  = KDIM * 2 + 16;   // B row pitch (bytes)
    constexpr int KT  = KDIM / 128;      // A k-chunks
    constexpr int NT  = NOUT / 32;       // n8-tiles per warp
    constexpr int NW  = NOUT / 4;        // warp n-width
    constexpr int RCB = KDIM / 8;        // uint4 per B row
    constexpr int AHI = 0;
    constexpr int BHI = 128 * PC;
    constexpr int BLO = BHI + NOUT * PB;
    constexpr int SAC = BLO + NOUT * PB;
    constexpr int SCC = SAC + NOUT * 4;

    extern __shared__ char smem[];
    const uint32_t sb = smem_u32(smem);
    const int tid = threadIdx.x, wid = tid >> 5, lane = tid & 31;
    const int wm = wid & 3, wn = wid >> 2;

    const __half* in = (MODE == 0) ? g_z16 : g_u16;
    const __half* Bsrc = (MODE == 0)
        ? (g_B1h + (size_t)l * 2 * HD2 * HD)
        : (g_B2h + (size_t)l * 2 * HD * HD2);

    for (int c = tid; c < 2 * NOUT * RCB; c += 512) {
        int buf = c / (NOUT * RCB);
        int rem = c - buf * NOUT * RCB;
        int n = rem / RCB, q = rem % RCB;
        const void* g = Bsrc + (size_t)c * 8;
        uint32_t s = sb + (buf ? BLO : BHI) + n * PB + q * 16;
        CP_ASYNC16(s, g, 16);
    }
    for (int c = tid; c < NOUT; c += 512) {
        float a = gm[c] * rsqrtf(vr[c] + 1e-5f);
        ((float*)(smem + SAC))[c] = a;
        ((float*)(smem + SCC))[c] = fmaf(a, bb[c] - mn[c], bt[c]);
    }
    CP_COMMIT();
    CP_WAIT0();
    __syncthreads();

    const float* Ac = (const float*)(smem + SAC);
    const float* Cc = (const float*)(smem + SCC);
    const uint32_t lrow = (lane & 15), lcol = (lane >> 4) * 16;
    const int tiles = (NN + 127) / 128;

    for (int tile = blockIdx.x; tile < tiles; tile += gridDim.x) {
        const int row0 = tile * 128;

        float acc[2][NT][4];
#pragma unroll
        for (int i = 0; i < 2; i++)
#pragma unroll
            for (int j = 0; j < NT; j++)
#pragma unroll
                for (int q = 0; q < 4; q++) acc[i][j][q] = 0.f;

#pragma unroll
        for (int kt = 0; kt < KT; kt++) {
            if (kt > 0) __syncthreads();
            // stage A chunk [128 rows x 128k] fp16
            for (int c = tid; c < 2048; c += 512) {
                int r = c >> 4, q = c & 15;
                int row = row0 + r;
                int ok = (row < NN);
                const void* g = in + (size_t)(ok ? row : 0) * KDIM + kt * 128 + q * 8;
                uint32_t s = sb + AHI + r * PC + q * 16;
                CP_ASYNC16(s, g, ok ? 16 : 0);
            }
            CP_COMMIT();
            CP_WAIT0();
            __syncthreads();

#pragma unroll
            for (int ks = 0; ks < 8; ks++) {
                uint32_t ah[2][4];
#pragma unroll
                for (int i = 0; i < 2; i++) {
                    uint32_t aAddr = sb + AHI + (wm * 32 + i * 16 + lrow) * PC + ks * 32 + lcol;
                    LDSM4(ah[i], aAddr);
                }
#pragma unroll
                for (int np = 0; np < NT / 2; np++) {
                    int n0 = wn * NW + np * 16;
                    uint32_t bAddr = sb + BHI + (n0 + lrow) * PB + (kt * 8 + ks) * 32 + lcol;
                    uint32_t bh[4], bl[4];
                    LDSM4(bh, bAddr);
                    LDSM4(bl, bAddr + (BLO - BHI));
#pragma unroll
                    for (int i = 0; i < 2; i++) {
                        MMA16816H(acc[i][2 * np],     ah[i], bh[0], bh[2]);
                        MMA16816H(acc[i][2 * np],     ah[i], bl[0], bl[2]);
                        MMA16816H(acc[i][2 * np + 1], ah[i], bh[1], bh[3]);
                        MMA16816H(acc[i][2 * np + 1], ah[i], bl[1], bl[3]);
                    }
                }
            }
        }

        // epilogue: BN + ReLU
#pragma unroll
        for (int i = 0; i < 2; i++) {
#pragma unroll
            for (int j = 0; j < NT; j++) {
                int r0 = row0 + wm * 32 + i * 16 + (lane >> 2);
                int r1 = r0 + 8;
                int c = wn * NW + j * 8 + (lane & 3) * 2;
                float a0 = Ac[c], a1 = Ac[c + 1], c0 = Cc[c], c1 = Cc[c + 1];
                float y00 = fmaxf(fmaf(acc[i][j][0], a0, c0), 0.f);
                float y01 = fmaxf(fmaf(acc[i][j][1], a1, c1), 0.f);
                float y10 = fmaxf(fmaf(acc[i][j][2], a0, c0), 0.f);
                float y11 = fmaxf(fmaf(acc[i][j][3], a1, c1), 0.f);
                if (MODE == 0) {
                    if (r0 < NN) {
                        __half2 p = __floats2half2_rn(y00, y01);
                        __stcs((uint32_t*)(g_u16 + (size_t)r0 * HD2 + c), *(uint32_t*)&p);
                    }
                    if (r1 < NN) {
                        __half2 p = __floats2half2_rn(y10, y11);
                        __stcs((uint32_t*)(g_u16 + (size_t)r1 * HD2 + c), *(uint32_t*)&p);
                    }
                } else {
                    if (r0 < NN) {
                        __half2 p = __floats2half2_rn(y00, y01);
                        *(uint32_t*)(g_h16 + (size_t)r0 * HD + c) = *(uint32_t*)&p;
                        if (last) *(float2*)(g_h + (size_t)r0 * HD + c) = make_float2(y00, y01);
                    }
                    if (r1 < NN) {
                        __half2 p = __floats2half2_rn(y10, y11);
                        *(uint32_t*)(g_h16 + (size_t)r1 * HD + c) = *(uint32_t*)&p;
                        if (last) *(float2*)(g_h + (size_t)r1 * HD + c) = make_float2(y10, y11);
                    }
                }
            }
        }
        __syncthreads();
    }
}

// ---------------- global mean pool (+ barrier reset for next replay) ----------
__global__ void k_pool(const int* __restrict__ batch, float* __restrict__ out) {
    if (blockIdx.x == 0 && threadIdx.x == 0) g_bar = 0;
    int g = blockIdx.x, c = threadIdx.x;
    int lo = 0, hi = NN;
    while (lo < hi) { int mid = (lo + hi) >> 1; if (batch[mid] < g) lo = mid + 1; else hi = mid; }
    int start = lo;
    lo = start; hi = NN;
    while (lo < hi) { int mid = (lo + hi) >> 1; if (batch[mid] < g + 1) lo = mid + 1; else hi = mid; }
    int end = lo;
    float acc = 0.f;
    int n = start;
    for (; n + 3 < end; n += 4) {
        acc += g_h[(n + 0) * HD + c];
        acc += g_h[(n + 1) * HD + c];
        acc += g_h[(n + 2) * HD + c];
        acc += g_h[(n + 3) * HD + c];
    }
    for (; n < end; n++) acc += g_h[n * HD + c];
    float cnt = (float)(end - start);
    out[g * HD + c] = acc / fmaxf(cnt, 1.f);
}

// ---------------- launch --------------------------------------------------------
extern "C" void kernel_launch(void* const* d_in, const int* in_sizes, int n_in,
                              void* d_out, int out_size) {
    const float* x    = (const float*)d_in[0];
    const int*   ei   = (const int*)d_in[1];
    const int*   bat  = (const int*)d_in[2];
    const float* Wemb = (const float*)d_in[3];
    const float* bemb = (const float*)d_in[4];
    const float* eps  = (const float*)d_in[5];
    const float* W1   = (const float*)d_in[6];
    const float* b1   = (const float*)d_in[7];
    const float* g1   = (const float*)d_in[8];
    const float* be1  = (const float*)d_in[9];
    const float* m1   = (const float*)d_in[10];
    const float* v1   = (const float*)d_in[11];
    const float* W2   = (const float*)d_in[12];
    const float* b2   = (const float*)d_in[13];
    const float* g2   = (const float*)d_in[14];
    const float* be2  = (const float*)d_in[15];
    const float* m2   = (const float*)d_in[16];
    const float* v2   = (const float*)d_in[17];
    float* out = (float*)d_out;

    // smem: MODE0 = 176128 B, MODE1 = 171008 B
    cudaFuncSetAttribute(k_gemm_mma<128, 256, 0>, cudaFuncAttributeMaxDynamicSharedMemorySize, 176128);
    cudaFuncSetAttribute(k_gemm_mma<256, 128, 1>, cudaFuncAttributeMaxDynamicSharedMemorySize, 171008);

    // launch order chosen so k_agg is the 4th launch (ncu captures launch #4)
    k_embed<<<(NN * HD + 255) / 256, 256>>>(x, Wemb, bemb);          // 1
    k_csr<<<CSRB, CSRT>>>(ei);                                       // 2
    k_packW1<<<(NL * HD2 * HD + 255) / 256, 256>>>(W1);              // 3

    for (int l = 0; l < NL; l++) {
        k_agg<<<(NN + 7) / 8, 256>>>(eps, l);                        // 4 (l=0)
        k_gemm_mma<128, 256, 0><<<148, 512, 176128>>>(l, 0, b1 + l * HD2, g1 + l * HD2,
                                                      be1 + l * HD2, m1 + l * HD2, v1 + l * HD2);
        if (l == 0) k_packW2<<<(NL * HD * HD2 + 255) / 256, 256>>>(W2);
        k_gemm_mma<256, 128, 1><<<148, 512, 171008>>>(l, (l == NL - 1) ? 1 : 0,
                                                      b2 + l * HD, g2 + l * HD,
                                                      be2 + l * HD, m2 + l * HD, v2 + l * HD);
    }

    k_pool<<<NG, 128>>>(bat, out);
}

// round 9
// speedup vs baseline: 1.5330x; 1.0321x over previous
#include <cuda_runtime.h>
#include <cuda_fp16.h>
#include <cstdint>

#define NN 100000
#define NE 3200000
#define HD 128
#define HD2 256
#define NL 4
#define NG 512
#define CSRB 296
#define CSRT 512
#define CHUNK 338   // ceil(NN/296)

// ---------------- PTX helpers (all plain-sm_103 legal) -------------------------
__device__ __forceinline__ uint32_t smem_u32(const void* p) {
    uint32_t a;
    asm("{ .reg .u64 t; cvta.to.shared.u64 t, %1; cvt.u32.u64 %0, t; }" : "=r"(a) : "l"(p));
    return a;
}
#define LDSM4(r, a) \
    asm volatile("ldmatrix.sync.aligned.m8n8.x4.shared.b16 {%0,%1,%2,%3}, [%4];" \
        : "=r"((r)[0]), "=r"((r)[1]), "=r"((r)[2]), "=r"((r)[3]) : "r"(a))
#define MMA16816H(d, a, b0, b1) \
    asm volatile("mma.sync.aligned.m16n8k16.row.col.f32.f16.f16.f32 " \
        "{%0,%1,%2,%3}, {%4,%5,%6,%7}, {%8,%9}, {%0,%1,%2,%3};" \
        : "+f"((d)[0]), "+f"((d)[1]), "+f"((d)[2]), "+f"((d)[3]) \
        : "r"((a)[0]), "r"((a)[1]), "r"((a)[2]), "r"((a)[3]), "r"(b0), "r"(b1))
#define CP_ASYNC16(s, g, sz) \
    asm volatile("cp.async.cg.shared.global [%0], [%1], 16, %2;" :: "r"(s), "l"(g), "r"(sz))
#define CP_COMMIT() asm volatile("cp.async.commit_group;")
#define CP_WAIT0()  asm volatile("cp.async.wait_group 0;")
#define CP_WAIT1()  asm volatile("cp.async.wait_group 1;")

// ---------------- device scratch ----------------------------------------------
__device__ __align__(16) float   g_h[NN * HD];               // fp32 h (last layer only, for pool)
__device__ __align__(16) __half  g_h16[NN * HD];             // fp16 h (agg input)
__device__ __align__(16) __half  g_z16[NN * HD];             // fp16 z (GEMM1 A)
__device__ __align__(16) __half  g_u16[(size_t)NN * HD2];    // fp16 u (GEMM2 A)
__device__ __align__(16) __half  g_B1h[NL * 2 * HD2 * HD];   // [l][hi|lo][n=256][k=128]
__device__ __align__(16) __half  g_B2h[NL * 2 * HD * HD2];   // [l][hi|lo][n=128][k=256]
__device__ int g_deg[NN], g_rowptr[NN + 1], g_cursor[NN], g_col[NE];
__device__ int g_part[CSRB], g_poff[CSRB];
__device__ volatile int g_bar;                               // reset by k_pool

// ---------------- grid-wide barrier (296 co-resident CTAs, 2/SM) ----------------
__device__ __forceinline__ void gridbar(int phase) {
    __syncthreads();
    if (threadIdx.x == 0) {
        __threadfence();
        atomicAdd((int*)&g_bar, 1);
        while (g_bar < CSRB * phase) { }
        __threadfence();
    }
    __syncthreads();
}

// ---------------- fused CSR build (one launch, 296x512) ------------------------
__global__ void __launch_bounds__(CSRT, 2) k_csr(const int* __restrict__ ei) {
    const int tid = threadIdx.x, bid = blockIdx.x;
    const int gstride = CSRB * CSRT;
    const int gtid = bid * CSRT + tid;
    __shared__ int s[CSRT];

    for (int i = gtid; i < NN; i += gstride) g_deg[i] = 0;
    gridbar(1);
    for (int e = gtid; e < NE; e += gstride) atomicAdd(&g_deg[ei[NE + e]], 1);
    gridbar(2);
    const int start = bid * CHUNK;
    const int end = (start + CHUNK < NN) ? start + CHUNK : NN;
    const int i0 = start + tid;                    // one node per thread (338 < 512)
    int own = (i0 < end) ? g_deg[i0] : 0;
    s[tid] = own;
    __syncthreads();
    for (int off = 1; off < CSRT; off <<= 1) {
        int t = (tid >= off) ? s[tid - off] : 0;
        __syncthreads(); s[tid] += t; __syncthreads();
    }
    const int texcl = s[tid] - own;
    if (tid == CSRT - 1) g_part[bid] = s[tid];
    gridbar(3);
    if (bid == 0 && tid == 0) {
        int r = 0;
        for (int b = 0; b < CSRB; b++) { g_poff[b] = r; r += g_part[b]; }
    }
    gridbar(4);
    if (i0 < end) {
        int run = g_poff[bid] + texcl;
        g_rowptr[i0] = run;
        g_cursor[i0] = run;
    }
    if (gtid == 0) g_rowptr[NN] = NE;
    gridbar(5);
    for (int e = gtid; e < NE; e += gstride) {
        int p = atomicAdd(&g_cursor[ei[NE + e]], 1);
        g_col[p] = ei[e];
    }
}

// ---------------- weight packing: [n][k] row-major fp16 hi/lo ------------------
__global__ void k_packW1(const float* __restrict__ W1) {
    int idx = blockIdx.x * blockDim.x + threadIdx.x;     // NL*256*128
    if (idx >= NL * HD2 * HD) return;
    int l = idx / (HD2 * HD), rem = idx % (HD2 * HD);
    int n = rem / HD, k = rem % HD;
    float w = W1[((size_t)l * HD + k) * HD2 + n];
    __half h = __float2half(w);
    __half lo = __float2half(w - __half2float(h));
    size_t base = (size_t)l * 2 * HD2 * HD;
    g_B1h[base + (size_t)n * HD + k] = h;
    g_B1h[base + (size_t)HD2 * HD + (size_t)n * HD + k] = lo;
}
__global__ void k_packW2(const float* __restrict__ W2) {
    int idx = blockIdx.x * blockDim.x + threadIdx.x;     // NL*128*256
    if (idx >= NL * HD * HD2) return;
    int l = idx / (HD * HD2), rem = idx % (HD * HD2);
    int n = rem / HD2, k = rem % HD2;
    float w = W2[((size_t)l * HD2 + k) * HD + n];
    __half h = __float2half(w);
    __half lo = __float2half(w - __half2float(h));
    size_t base = (size_t)l * 2 * HD * HD2;
    g_B2h[base + (size_t)n * HD2 + k] = h;
    g_B2h[base + (size_t)HD * HD2 + (size_t)n * HD2 + k] = lo;
}

// ---------------- atom embedding (h16 only) -------------------------------------
__global__ void k_embed(const float* __restrict__ x, const float* __restrict__ W,
                        const float* __restrict__ b) {
    int idx = blockIdx.x * blockDim.x + threadIdx.x;
    if (idx >= NN * HD) return;
    int n = idx >> 7, c = idx & 127;
    const float* xr = x + n * 9;
    float acc = b[c];
#pragma unroll
    for (int k = 0; k < 9; k++) acc = fmaf(xr[k], W[k * HD + c], acc);
    g_h16[idx] = __float2half(acc);
}

// ---------------- GIN aggregation: packed fp16 batch accumulate -----------------
// Batches of 8 neighbors summed with HADD2 (2 independent chains), flushed to
// fp32 per batch. Remainder edges accumulated in fp32.
__global__ void k_agg(const float* __restrict__ eps, int l) {
    int node = (blockIdx.x * blockDim.x + threadIdx.x) >> 5;
    if (node >= NN) return;
    int lane = threadIdx.x & 31;
    const uint2* h16 = (const uint2*)g_h16;   // row = 32 uint2 (4 halves each)
    float sc = 1.0f + eps[l];
    uint2 sv = h16[(size_t)node * 32 + lane];
    float2 f0 = __half22float2(*(__half2*)&sv.x);
    float2 f1 = __half22float2(*(__half2*)&sv.y);
    float ax = f0.x * sc, ay = f0.y * sc, az = f1.x * sc, aw = f1.y * sc;
    int j = g_rowptr[node], e = g_rowptr[node + 1];
    for (; j + 7 < e; j += 8) {
        __half2 z = __float2half2_rn(0.f);
        __half2 sa0 = z, sa1 = z, sb0 = z, sb1 = z;
#pragma unroll
        for (int q = 0; q < 8; q += 2) {
            uint2 va = h16[(size_t)g_col[j + q]     * 32 + lane];
            uint2 vb = h16[(size_t)g_col[j + q + 1] * 32 + lane];
            sa0 = __hadd2(sa0, *(__half2*)&va.x);
            sa1 = __hadd2(sa1, *(__half2*)&va.y);
            sb0 = __hadd2(sb0, *(__half2*)&vb.x);
            sb1 = __hadd2(sb1, *(__half2*)&vb.y);
        }
        float2 f;
        f = __half22float2(sa0); ax += f.x; ay += f.y;
        f = __half22float2(sa1); az += f.x; aw += f.y;
        f = __half22float2(sb0); ax += f.x; ay += f.y;
        f = __half22float2(sb1); az += f.x; aw += f.y;
    }
    for (; j < e; j++) {
        uint2 v = h16[(size_t)g_col[j] * 32 + lane];
        float2 f;
        f = __half22float2(*(__half2*)&v.x); ax += f.x; ay += f.y;
        f = __half22float2(*(__half2*)&v.y); az += f.x; aw += f.y;
    }
    __half2 p0 = __floats2half2_rn(ax, ay);
    __half2 p1 = __floats2half2_rn(az, aw);
    uint2 ov = make_uint2(*(uint32_t*)&p0, *(uint32_t*)&p1);
    __stcs((uint2*)(g_z16 + (size_t)node * HD) + lane, ov);
}

// ---------------- HMMA GEMM + BN + ReLU (fp16 A x fp16 hi/lo B, 2 terms) --------
// MODE 0: u16 = relu(BN(z @ W1)), KDIM=128, NOUT=256
// MODE 1: h16 (+h fp32 if last) = relu(BN(u @ W2)), KDIM=256, NOUT=128
// A chunks double-buffered via cp.async across the flattened (tile, kchunk) loop.
template <int KDIM, int NOUT, int MODE>
__global__ void __launch_bounds__(512, 1)
k_gemm_mma(int l, int last, const float* __restrict__ bb, const float* __restrict__ gm,
           const float* __restrict__ bt, const float* __restrict__ mn,
           const float* __restrict__ vr) {
    constexpr int PC  = 128 * 2 + 16;    // A chunk pitch (bytes)
    constexpr int PB  = KDIM * 2 + 16;   // B row pitch (bytes)
    constexpr int KT  = KDIM / 128;      // A k-chunks per tile
    constexpr int NT  = NOUT / 32;       // n8-tiles per warp
    constexpr int NW  = NOUT / 4;        // warp n-width
    constexpr int RCB = KDIM / 8;        // uint4 per B row
    constexpr int ACH = 128 * PC;        // A chunk bytes
    constexpr int BHI = 2 * ACH;
    constexpr int BLO = BHI + NOUT * PB;
    constexpr int SAC = BLO + NOUT * PB;
    constexpr int SCC = SAC + NOUT * 4;

    extern __shared__ char smem[];
    const uint32_t sb = smem_u32(smem);
    const int tid = threadIdx.x, wid = tid >> 5, lane = tid & 31;
    const int wm = wid & 3, wn = wid >> 2;

    const __half* in = (MODE == 0) ? g_z16 : g_u16;
    const __half* Bsrc = (MODE == 0)
        ? (g_B1h + (size_t)l * 2 * HD2 * HD)
        : (g_B2h + (size_t)l * 2 * HD * HD2);

    for (int c = tid; c < 2 * NOUT * RCB; c += 512) {
        int buf = c / (NOUT * RCB);
        int rem = c - buf * NOUT * RCB;
        int n = rem / RCB, q = rem % RCB;
        const void* g = Bsrc + (size_t)c * 8;
        uint32_t s = sb + (buf ? BLO : BHI) + n * PB + q * 16;
        CP_ASYNC16(s, g, 16);
    }
    for (int c = tid; c < NOUT; c += 512) {
        float a = gm[c] * rsqrtf(vr[c] + 1e-5f);
        ((float*)(smem + SAC))[c] = a;
        ((float*)(smem + SCC))[c] = fmaf(a, bb[c] - mn[c], bt[c]);
    }
    CP_COMMIT();
    CP_WAIT0();
    __syncthreads();

    const float* Ac = (const float*)(smem + SAC);
    const float* Cc = (const float*)(smem + SCC);
    const uint32_t lrow = (lane & 15), lcol = (lane >> 4) * 16;
    const int tiles = (NN + 127) / 128;
    const int myTiles = (tiles > (int)blockIdx.x)
                        ? (tiles - blockIdx.x + gridDim.x - 1) / gridDim.x : 0;
    const int nchunks = myTiles * KT;

    auto issueA = [&](int chunk, int buf) {
        int tIdx = chunk / KT, kt = chunk % KT;
        int row0 = (blockIdx.x + tIdx * gridDim.x) * 128;
        for (int c = tid; c < 2048; c += 512) {
            int r = c >> 4, q = c & 15;
            int row = row0 + r;
            int ok = (row < NN);
            const void* g = in + (size_t)(ok ? row : 0) * KDIM + kt * 128 + q * 8;
            uint32_t s = sb + buf * ACH + r * PC + q * 16;
            CP_ASYNC16(s, g, ok ? 16 : 0);
        }
        CP_COMMIT();
    };

    float acc[2][NT][4];
#pragma unroll
    for (int i = 0; i < 2; i++)
#pragma unroll
        for (int j = 0; j < NT; j++)
#pragma unroll
            for (int q = 0; q < 4; q++) acc[i][j][q] = 0.f;

    if (nchunks > 0) issueA(0, 0);

    for (int ch = 0; ch < nchunks; ch++) {
        const int kt = ch % KT;
        const int tile = blockIdx.x + (ch / KT) * gridDim.x;
        const int buf = ch & 1;
        if (ch + 1 < nchunks) { issueA(ch + 1, (ch + 1) & 1); CP_WAIT1(); }
        else                  { CP_WAIT0(); }
        __syncthreads();

#pragma unroll
        for (int ks = 0; ks < 8; ks++) {
            uint32_t ah[2][4];
#pragma unroll
            for (int i = 0; i < 2; i++) {
                uint32_t aAddr = sb + buf * ACH + (wm * 32 + i * 16 + lrow) * PC + ks * 32 + lcol;
                LDSM4(ah[i], aAddr);
            }
#pragma unroll
            for (int np = 0; np < NT / 2; np++) {
                int n0 = wn * NW + np * 16;
                uint32_t bAddr = sb + BHI + (n0 + lrow) * PB + (kt * 8 + ks) * 32 + lcol;
                uint32_t bh[4], bl[4];
                LDSM4(bh, bAddr);
                LDSM4(bl, bAddr + (BLO - BHI));
#pragma unroll
                for (int i = 0; i < 2; i++) {
                    MMA16816H(acc[i][2 * np],     ah[i], bh[0], bh[2]);
                    MMA16816H(acc[i][2 * np],     ah[i], bl[0], bl[2]);
                    MMA16816H(acc[i][2 * np + 1], ah[i], bh[1], bh[3]);
                    MMA16816H(acc[i][2 * np + 1], ah[i], bl[1], bl[3]);
                }
            }
        }

        if (kt == KT - 1) {
            const int row0 = tile * 128;
#pragma unroll
            for (int i = 0; i < 2; i++) {
#pragma unroll
                for (int j = 0; j < NT; j++) {
                    int r0 = row0 + wm * 32 + i * 16 + (lane >> 2);
                    int r1 = r0 + 8;
                    int c = wn * NW + j * 8 + (lane & 3) * 2;
                    float a0 = Ac[c], a1 = Ac[c + 1], c0 = Cc[c], c1 = Cc[c + 1];
                    float y00 = fmaxf(fmaf(acc[i][j][0], a0, c0), 0.f);
                    float y01 = fmaxf(fmaf(acc[i][j][1], a1, c1), 0.f);
                    float y10 = fmaxf(fmaf(acc[i][j][2], a0, c0), 0.f);
                    float y11 = fmaxf(fmaf(acc[i][j][3], a1, c1), 0.f);
                    if (MODE == 0) {
                        if (r0 < NN) {
                            __half2 p = __floats2half2_rn(y00, y01);
                            __stcs((uint32_t*)(g_u16 + (size_t)r0 * HD2 + c), *(uint32_t*)&p);
                        }
                        if (r1 < NN) {
                            __half2 p = __floats2half2_rn(y10, y11);
                            __stcs((uint32_t*)(g_u16 + (size_t)r1 * HD2 + c), *(uint32_t*)&p);
                        }
                    } else {
                        if (r0 < NN) {
                            __half2 p = __floats2half2_rn(y00, y01);
                            *(uint32_t*)(g_h16 + (size_t)r0 * HD + c) = *(uint32_t*)&p;
                            if (last) *(float2*)(g_h + (size_t)r0 * HD + c) = make_float2(y00, y01);
                        }
                        if (r1 < NN) {
                            __half2 p = __floats2half2_rn(y10, y11);
                            *(uint32_t*)(g_h16 + (size_t)r1 * HD + c) = *(uint32_t*)&p;
                            if (last) *(float2*)(g_h + (size_t)r1 * HD + c) = make_float2(y10, y11);
                        }
                    }
#pragma unroll
                    for (int q = 0; q < 4; q++) acc[i][j][q] = 0.f;
                }
            }
        }
        __syncthreads();
    }
}

// ---------------- global mean pool (+ barrier reset for next replay) ----------
__global__ void k_pool(const int* __restrict__ batch, float* __restrict__ out) {
    if (blockIdx.x == 0 && threadIdx.x == 0) g_bar = 0;
    int g = blockIdx.x, c = threadIdx.x;
    int lo = 0, hi = NN;
    while (lo < hi) { int mid = (lo + hi) >> 1; if (batch[mid] < g) lo = mid + 1; else hi = mid; }
    int start = lo;
    lo = start; hi = NN;
    while (lo < hi) { int mid = (lo + hi) >> 1; if (batch[mid] < g + 1) lo = mid + 1; else hi = mid; }
    int end = lo;
    float acc = 0.f;
    int n = start;
    for (; n + 3 < end; n += 4) {
        acc += g_h[(n + 0) * HD + c];
        acc += g_h[(n + 1) * HD + c];
        acc += g_h[(n + 2) * HD + c];
        acc += g_h[(n + 3) * HD + c];
    }
    for (; n < end; n++) acc += g_h[n * HD + c];
    float cnt = (float)(end - start);
    out[g * HD + c] = acc / fmaxf(cnt, 1.f);
}

// ---------------- launch --------------------------------------------------------
extern "C" void kernel_launch(void* const* d_in, const int* in_sizes, int n_in,
                              void* d_out, int out_size) {
    const float* x    = (const float*)d_in[0];
    const int*   ei   = (const int*)d_in[1];
    const int*   bat  = (const int*)d_in[2];
    const float* Wemb = (const float*)d_in[3];
    const float* bemb = (const float*)d_in[4];
    const float* eps  = (const float*)d_in[5];
    const float* W1   = (const float*)d_in[6];
    const float* b1   = (const float*)d_in[7];
    const float* g1   = (const float*)d_in[8];
    const float* be1  = (const float*)d_in[9];
    const float* m1   = (const float*)d_in[10];
    const float* v1   = (const float*)d_in[11];
    const float* W2   = (const float*)d_in[12];
    const float* b2   = (const float*)d_in[13];
    const float* g2   = (const float*)d_in[14];
    const float* be2  = (const float*)d_in[15];
    const float* m2   = (const float*)d_in[16];
    const float* v2   = (const float*)d_in[17];
    float* out = (float*)d_out;

    // smem: MODE0 = 210944 B, MODE1 = 205824 B
    cudaFuncSetAttribute(k_gemm_mma<128, 256, 0>, cudaFuncAttributeMaxDynamicSharedMemorySize, 210944);
    cudaFuncSetAttribute(k_gemm_mma<256, 128, 1>, cudaFuncAttributeMaxDynamicSharedMemorySize, 205824);

    k_embed<<<(NN * HD + 255) / 256, 256>>>(x, Wemb, bemb);          // 1
    k_csr<<<CSRB, CSRT>>>(ei);                                       // 2
    k_packW1<<<(NL * HD2 * HD + 255) / 256, 256>>>(W1);              // 3

    for (int l = 0; l < NL; l++) {
        k_agg<<<(NN + 7) / 8, 256>>>(eps, l);                        // 4 (l=0)
        k_gemm_mma<128, 256, 0><<<148, 512, 210944>>>(l, 0, b1 + l * HD2, g1 + l * HD2,
                                                      be1 + l * HD2, m1 + l * HD2, v1 + l * HD2);
        if (l == 0) k_packW2<<<(NL * HD * HD2 + 255) / 256, 256>>>(W2);
        k_gemm_mma<256, 128, 1><<<148, 512, 205824>>>(l, (l == NL - 1) ? 1 : 0,
                                                      b2 + l * HD, g2 + l * HD,
                                                      be2 + l * HD, m2 + l * HD, v2 + l * HD);
    }

    k_pool<<<NG, 128>>>(bat, out);
}

// round 10
// speedup vs baseline: 1.8333x; 1.1959x over previous
#include <cuda_runtime.h>
#include <cuda_fp16.h>
#include <cstdint>

#define NN 100000
#define NE 3200000
#define HD 128
#define HD2 256
#define NL 4
#define NG 512
#define CSRB 296
#define CSRT 512
#define CHUNK 338    // ceil(NN/296)
#define EMB_B 50000  // embed blocks (NN*HD/256)
#define PK_B 512     // pack blocks per weight tensor

// ---------------- PTX helpers (all plain-sm_103 legal) -------------------------
__device__ __forceinline__ uint32_t smem_u32(const void* p) {
    uint32_t a;
    asm("{ .reg .u64 t; cvta.to.shared.u64 t, %1; cvt.u32.u64 %0, t; }" : "=r"(a) : "l"(p));
    return a;
}
#define LDSM4(r, a) \
    asm volatile("ldmatrix.sync.aligned.m8n8.x4.shared.b16 {%0,%1,%2,%3}, [%4];" \
        : "=r"((r)[0]), "=r"((r)[1]), "=r"((r)[2]), "=r"((r)[3]) : "r"(a))
#define MMA16816H(d, a, b0, b1) \
    asm volatile("mma.sync.aligned.m16n8k16.row.col.f32.f16.f16.f32 " \
        "{%0,%1,%2,%3}, {%4,%5,%6,%7}, {%8,%9}, {%0,%1,%2,%3};" \
        : "+f"((d)[0]), "+f"((d)[1]), "+f"((d)[2]), "+f"((d)[3]) \
        : "r"((a)[0]), "r"((a)[1]), "r"((a)[2]), "r"((a)[3]), "r"(b0), "r"(b1))
#define CP_ASYNC16(s, g, sz) \
    asm volatile("cp.async.cg.shared.global [%0], [%1], 16, %2;" :: "r"(s), "l"(g), "r"(sz))
#define CP_COMMIT() asm volatile("cp.async.commit_group;")
#define CP_WAIT0()  asm volatile("cp.async.wait_group 0;")
#define CP_WAIT1()  asm volatile("cp.async.wait_group 1;")

// ---------------- device scratch ----------------------------------------------
__device__ __align__(16) float   g_h[NN * HD];               // fp32 h (last layer only, for pool)
__device__ __align__(16) __half  g_h16[NN * HD];             // fp16 h (agg input)
__device__ __align__(16) __half  g_z16[NN * HD];             // fp16 z (GEMM1 A)
__device__ __align__(16) __half  g_u16[(size_t)NN * HD2];    // fp16 u (GEMM2 A)
__device__ __align__(16) __half  g_B1h[NL * HD2 * HD];       // [l][n=256][k=128] fp16
__device__ __align__(16) __half  g_B2h[NL * HD * HD2];       // [l][n=128][k=256] fp16
__device__ int g_deg[NN], g_rowptr[NN + 1], g_cursor[NN], g_col[NE];
__device__ int g_part[CSRB], g_poff[CSRB];
__device__ volatile int g_bar;                               // reset by k_pool

// ---------------- grid-wide barrier (296 co-resident CTAs, 2/SM) ----------------
__device__ __forceinline__ void gridbar(int phase) {
    __syncthreads();
    if (threadIdx.x == 0) {
        __threadfence();
        atomicAdd((int*)&g_bar, 1);
        while (g_bar < CSRB * phase) { }
        __threadfence();
    }
    __syncthreads();
}

// ---------------- fused CSR build (one launch, 296x512) ------------------------
__global__ void __launch_bounds__(CSRT, 2) k_csr(const int* __restrict__ ei) {
    const int tid = threadIdx.x, bid = blockIdx.x;
    const int gstride = CSRB * CSRT;
    const int gtid = bid * CSRT + tid;
    __shared__ int s[CSRT];

    for (int i = gtid; i < NN; i += gstride) g_deg[i] = 0;
    gridbar(1);
    for (int e = gtid; e < NE; e += gstride) atomicAdd(&g_deg[ei[NE + e]], 1);
    gridbar(2);
    const int start = bid * CHUNK;
    const int end = (start + CHUNK < NN) ? start + CHUNK : NN;
    const int i0 = start + tid;                    // one node per thread (338 < 512)
    int own = (i0 < end) ? g_deg[i0] : 0;
    s[tid] = own;
    __syncthreads();
    for (int off = 1; off < CSRT; off <<= 1) {
        int t = (tid >= off) ? s[tid - off] : 0;
        __syncthreads(); s[tid] += t; __syncthreads();
    }
    const int texcl = s[tid] - own;
    if (tid == CSRT - 1) g_part[bid] = s[tid];
    gridbar(3);
    if (bid == 0 && tid == 0) {
        int r = 0;
        for (int b = 0; b < CSRB; b++) { g_poff[b] = r; r += g_part[b]; }
    }
    gridbar(4);
    if (i0 < end) {
        int run = g_poff[bid] + texcl;
        g_rowptr[i0] = run;
        g_cursor[i0] = run;
    }
    if (gtid == 0) g_rowptr[NN] = NE;
    gridbar(5);
    for (int e = gtid; e < NE; e += gstride) {
        int p = atomicAdd(&g_cursor[ei[NE + e]], 1);
        g_col[p] = ei[e];
    }
}

// ---------------- fused embed + weight packing ----------------------------------
// bid < EMB_B: atom embedding (h16). Next PK_B blocks: pack W1. Next PK_B: pack W2.
__global__ void k_embed_pack(const float* __restrict__ x, const float* __restrict__ Wemb,
                             const float* __restrict__ bemb,
                             const float* __restrict__ W1, const float* __restrict__ W2) {
    int bid = blockIdx.x;
    int tid = threadIdx.x;
    if (bid < EMB_B) {
        int idx = bid * 256 + tid;
        int n = idx >> 7, c = idx & 127;
        const float* xr = x + n * 9;
        float acc = bemb[c];
#pragma unroll
        for (int k = 0; k < 9; k++) acc = fmaf(xr[k], Wemb[k * HD + c], acc);
        g_h16[idx] = __float2half(acc);
    } else if (bid < EMB_B + PK_B) {
        int idx = (bid - EMB_B) * 256 + tid;        // NL*256*128
        int l = idx / (HD2 * HD), rem = idx % (HD2 * HD);
        int n = rem / HD, k = rem % HD;
        float w = W1[((size_t)l * HD + k) * HD2 + n];
        g_B1h[(size_t)l * HD2 * HD + (size_t)n * HD + k] = __float2half(w);
    } else {
        int idx = (bid - EMB_B - PK_B) * 256 + tid; // NL*128*256
        int l = idx / (HD * HD2), rem = idx % (HD * HD2);
        int n = rem / HD2, k = rem % HD2;
        float w = W2[((size_t)l * HD2 + k) * HD + n];
        g_B2h[(size_t)l * HD * HD2 + (size_t)n * HD2 + k] = __float2half(w);
    }
}

// ---------------- GIN aggregation: fp16 gather, fp32 accumulate -----------------
__global__ void k_agg(const float* __restrict__ eps, int l) {
    int node = (blockIdx.x * blockDim.x + threadIdx.x) >> 5;
    if (node >= NN) return;
    int lane = threadIdx.x & 31;
    const uint2* h16 = (const uint2*)g_h16;   // row = 32 uint2 (4 halves each)
    float sc = 1.0f + eps[l];
    uint2 sv = h16[(size_t)node * 32 + lane];
    float2 f0 = __half22float2(*(__half2*)&sv.x);
    float2 f1 = __half22float2(*(__half2*)&sv.y);
    float ax = f0.x * sc, ay = f0.y * sc, az = f1.x * sc, aw = f1.y * sc;
    int j = g_rowptr[node], e = g_rowptr[node + 1];
    for (; j + 3 < e; j += 4) {
        uint2 v0 = h16[(size_t)g_col[j]     * 32 + lane];
        uint2 v1 = h16[(size_t)g_col[j + 1] * 32 + lane];
        uint2 v2 = h16[(size_t)g_col[j + 2] * 32 + lane];
        uint2 v3 = h16[(size_t)g_col[j + 3] * 32 + lane];
        float2 f;
        f = __half22float2(*(__half2*)&v0.x); ax += f.x; ay += f.y;
        f = __half22float2(*(__half2*)&v0.y); az += f.x; aw += f.y;
        f = __half22float2(*(__half2*)&v1.x); ax += f.x; ay += f.y;
        f = __half22float2(*(__half2*)&v1.y); az += f.x; aw += f.y;
        f = __half22float2(*(__half2*)&v2.x); ax += f.x; ay += f.y;
        f = __half22float2(*(__half2*)&v2.y); az += f.x; aw += f.y;
        f = __half22float2(*(__half2*)&v3.x); ax += f.x; ay += f.y;
        f = __half22float2(*(__half2*)&v3.y); az += f.x; aw += f.y;
    }
    for (; j < e; j++) {
        uint2 v = h16[(size_t)g_col[j] * 32 + lane];
        float2 f;
        f = __half22float2(*(__half2*)&v.x); ax += f.x; ay += f.y;
        f = __half22float2(*(__half2*)&v.y); az += f.x; aw += f.y;
    }
    __half2 p0 = __floats2half2_rn(ax, ay);
    __half2 p1 = __floats2half2_rn(az, aw);
    uint2 ov = make_uint2(*(uint32_t*)&p0, *(uint32_t*)&p1);
    __stcs((uint2*)(g_z16 + (size_t)node * HD) + lane, ov);
}

// ---------------- HMMA GEMM + BN + ReLU (single-term fp16) ----------------------
// MODE 0: u16 = relu(BN(z @ W1)), KDIM=128, NOUT=256
// MODE 1: h16 (+h fp32 if last) = relu(BN(u @ W2)), KDIM=256, NOUT=128
// A chunks double-buffered via cp.async across the flattened (tile, kchunk) loop.
template <int KDIM, int NOUT, int MODE>
__global__ void __launch_bounds__(512, 1)
k_gemm_mma(int l, int last, const float* __restrict__ bb, const float* __restrict__ gm,
           const float* __restrict__ bt, const float* __restrict__ mn,
           const float* __restrict__ vr) {
    constexpr int PC  = 128 * 2 + 16;    // A chunk pitch (bytes)
    constexpr int PB  = KDIM * 2 + 16;   // B row pitch (bytes)
    constexpr int KT  = KDIM / 128;      // A k-chunks per tile
    constexpr int NT  = NOUT / 32;       // n8-tiles per warp
    constexpr int NW  = NOUT / 4;        // warp n-width
    constexpr int RCB = KDIM / 8;        // uint4 per B row
    constexpr int ACH = 128 * PC;        // A chunk bytes
    constexpr int BHI = 2 * ACH;
    constexpr int SAC = BHI + NOUT * PB;
    constexpr int SCC = SAC + NOUT * 4;

    extern __shared__ char smem[];
    const uint32_t sb = smem_u32(smem);
    const int tid = threadIdx.x, wid = tid >> 5, lane = tid & 31;
    const int wm = wid & 3, wn = wid >> 2;

    const __half* in = (MODE == 0) ? g_z16 : g_u16;
    const __half* Bsrc = (MODE == 0)
        ? (g_B1h + (size_t)l * HD2 * HD)
        : (g_B2h + (size_t)l * HD * HD2);

    for (int c = tid; c < NOUT * RCB; c += 512) {
        int n = c / RCB, q = c % RCB;
        const void* g = Bsrc + (size_t)c * 8;
        uint32_t s = sb + BHI + n * PB + q * 16;
        CP_ASYNC16(s, g, 16);
    }
    for (int c = tid; c < NOUT; c += 512) {
        float a = gm[c] * rsqrtf(vr[c] + 1e-5f);
        ((float*)(smem + SAC))[c] = a;
        ((float*)(smem + SCC))[c] = fmaf(a, bb[c] - mn[c], bt[c]);
    }
    CP_COMMIT();
    CP_WAIT0();
    __syncthreads();

    const float* Ac = (const float*)(smem + SAC);
    const float* Cc = (const float*)(smem + SCC);
    const uint32_t lrow = (lane & 15), lcol = (lane >> 4) * 16;
    const int tiles = (NN + 127) / 128;
    const int myTiles = (tiles > (int)blockIdx.x)
                        ? (tiles - blockIdx.x + gridDim.x - 1) / gridDim.x : 0;
    const int nchunks = myTiles * KT;

    auto issueA = [&](int chunk, int buf) {
        int tIdx = chunk / KT, kt = chunk % KT;
        int row0 = (blockIdx.x + tIdx * gridDim.x) * 128;
        for (int c = tid; c < 2048; c += 512) {
            int r = c >> 4, q = c & 15;
            int row = row0 + r;
            int ok = (row < NN);
            const void* g = in + (size_t)(ok ? row : 0) * KDIM + kt * 128 + q * 8;
            uint32_t s = sb + buf * ACH + r * PC + q * 16;
            CP_ASYNC16(s, g, ok ? 16 : 0);
        }
        CP_COMMIT();
    };

    float acc[2][NT][4];
#pragma unroll
    for (int i = 0; i < 2; i++)
#pragma unroll
        for (int j = 0; j < NT; j++)
#pragma unroll
            for (int q = 0; q < 4; q++) acc[i][j][q] = 0.f;

    if (nchunks > 0) issueA(0, 0);

    for (int ch = 0; ch < nchunks; ch++) {
        const int kt = ch % KT;
        const int tile = blockIdx.x + (ch / KT) * gridDim.x;
        const int buf = ch & 1;
        if (ch + 1 < nchunks) { issueA(ch + 1, (ch + 1) & 1); CP_WAIT1(); }
        else                  { CP_WAIT0(); }
        __syncthreads();

#pragma unroll
        for (int ks = 0; ks < 8; ks++) {
            uint32_t ah[2][4];
#pragma unroll
            for (int i = 0; i < 2; i++) {
                uint32_t aAddr = sb + buf * ACH + (wm * 32 + i * 16 + lrow) * PC + ks * 32 + lcol;
                LDSM4(ah[i], aAddr);
            }
#pragma unroll
            for (int np = 0; np < NT / 2; np++) {
                int n0 = wn * NW + np * 16;
                uint32_t bAddr = sb + BHI + (n0 + lrow) * PB + (kt * 8 + ks) * 32 + lcol;
                uint32_t bh[4];
                LDSM4(bh, bAddr);
#pragma unroll
                for (int i = 0; i < 2; i++) {
                    MMA16816H(acc[i][2 * np],     ah[i], bh[0], bh[2]);
                    MMA16816H(acc[i][2 * np + 1], ah[i], bh[1], bh[3]);
                }
            }
        }

        if (kt == KT - 1) {
            const int row0 = tile * 128;
#pragma unroll
            for (int i = 0; i < 2; i++) {
#pragma unroll
                for (int j = 0; j < NT; j++) {
                    int r0 = row0 + wm * 32 + i * 16 + (lane >> 2);
                    int r1 = r0 + 8;
                    int c = wn * NW + j * 8 + (lane & 3) * 2;
                    float a0 = Ac[c], a1 = Ac[c + 1], c0 = Cc[c], c1 = Cc[c + 1];
                    float y00 = fmaxf(fmaf(acc[i][j][0], a0, c0), 0.f);
                    float y01 = fmaxf(fmaf(acc[i][j][1], a1, c1), 0.f);
                    float y10 = fmaxf(fmaf(acc[i][j][2], a0, c0), 0.f);
                    float y11 = fmaxf(fmaf(acc[i][j][3], a1, c1), 0.f);
                    if (MODE == 0) {
                        if (r0 < NN) {
                            __half2 p = __floats2half2_rn(y00, y01);
                            __stcs((uint32_t*)(g_u16 + (size_t)r0 * HD2 + c), *(uint32_t*)&p);
                        }
                        if (r1 < NN) {
                            __half2 p = __floats2half2_rn(y10, y11);
                            __stcs((uint32_t*)(g_u16 + (size_t)r1 * HD2 + c), *(uint32_t*)&p);
                        }
                    } else {
                        if (r0 < NN) {
                            __half2 p = __floats2half2_rn(y00, y01);
                            *(uint32_t*)(g_h16 + (size_t)r0 * HD + c) = *(uint32_t*)&p;
                            if (last) *(float2*)(g_h + (size_t)r0 * HD + c) = make_float2(y00, y01);
                        }
                        if (r1 < NN) {
                            __half2 p = __floats2half2_rn(y10, y11);
                            *(uint32_t*)(g_h16 + (size_t)r1 * HD + c) = *(uint32_t*)&p;
                            if (last) *(float2*)(g_h + (size_t)r1 * HD + c) = make_float2(y10, y11);
                        }
                    }
#pragma unroll
                    for (int q = 0; q < 4; q++) acc[i][j][q] = 0.f;
                }
            }
        }
        __syncthreads();
    }
}

// ---------------- global mean pool (+ barrier reset for next replay) ----------
__global__ void k_pool(const int* __restrict__ batch, float* __restrict__ out) {
    if (blockIdx.x == 0 && threadIdx.x == 0) g_bar = 0;
    int g = blockIdx.x, c = threadIdx.x;
    int lo = 0, hi = NN;
    while (lo < hi) { int mid = (lo + hi) >> 1; if (batch[mid] < g) lo = mid + 1; else hi = mid; }
    int start = lo;
    lo = start; hi = NN;
    while (lo < hi) { int mid = (lo + hi) >> 1; if (batch[mid] < g + 1) lo = mid + 1; else hi = mid; }
    int end = lo;
    float acc = 0.f;
    int n = start;
    for (; n + 3 < end; n += 4) {
        acc += g_h[(n + 0) * HD + c];
        acc += g_h[(n + 1) * HD + c];
        acc += g_h[(n + 2) * HD + c];
        acc += g_h[(n + 3) * HD + c];
    }
    for (; n < end; n++) acc += g_h[n * HD + c];
    float cnt = (float)(end - start);
    out[g * HD + c] = acc / fmaxf(cnt, 1.f);
}

// ---------------- launch --------------------------------------------------------
extern "C" void kernel_launch(void* const* d_in, const int* in_sizes, int n_in,
                              void* d_out, int out_size) {
    const float* x    = (const float*)d_in[0];
    const int*   ei   = (const int*)d_in[1];
    const int*   bat  = (const int*)d_in[2];
    const float* Wemb = (const float*)d_in[3];
    const float* bemb = (const float*)d_in[4];
    const float* eps  = (const float*)d_in[5];
    const float* W1   = (const float*)d_in[6];
    const float* b1   = (const float*)d_in[7];
    const float* g1   = (const float*)d_in[8];
    const float* be1  = (const float*)d_in[9];
    const float* m1   = (const float*)d_in[10];
    const float* v1   = (const float*)d_in[11];
    const float* W2   = (const float*)d_in[12];
    const float* b2   = (const float*)d_in[13];
    const float* g2   = (const float*)d_in[14];
    const float* be2  = (const float*)d_in[15];
    const float* m2   = (const float*)d_in[16];
    const float* v2   = (const float*)d_in[17];
    float* out = (float*)d_out;

    // smem: MODE0 = 141312 B, MODE1 = 138240 B
    cudaFuncSetAttribute(k_gemm_mma<128, 256, 0>, cudaFuncAttributeMaxDynamicSharedMemorySize, 141312);
    cudaFuncSetAttribute(k_gemm_mma<256, 128, 1>, cudaFuncAttributeMaxDynamicSharedMemorySize, 138240);

    // order: embed+pack(1), csr(2), agg(3), gemm1(4) -> ncu (launch #4) profiles gemm1
    k_embed_pack<<<EMB_B + 2 * PK_B, 256>>>(x, Wemb, bemb, W1, W2);  // 1
    k_csr<<<CSRB, CSRT>>>(ei);                                       // 2

    for (int l = 0; l < NL; l++) {
        k_agg<<<(NN + 7) / 8, 256>>>(eps, l);                        // 3 (l=0)
        k_gemm_mma<128, 256, 0><<<148, 512, 141312>>>(l, 0, b1 + l * HD2, g1 + l * HD2,
                                                      be1 + l * HD2, m1 + l * HD2, v1 + l * HD2);
        k_gemm_mma<256, 128, 1><<<148, 512, 138240>>>(l, (l == NL - 1) ? 1 : 0,
                                                      b2 + l * HD, g2 + l * HD,
                                                      be2 + l * HD, m2 + l * HD, v2 + l * HD);
    }

    k_pool<<<NG, 128>>>(bat, out);
}

// round 11
// speedup vs baseline: 1.9105x; 1.0421x over previous
#include <cuda_runtime.h>
#include <cuda_fp16.h>
#include <cstdint>

#define NN 100000
#define NE 3200000
#define HD 128
#define HD2 256
#define NL 4
#define NG 512
#define CSRB 296
#define CSRT 512
#define CHUNK 338    // ceil(NN/296)
#define EMB_B 50000  // embed blocks (NN*HD/256)
#define PK_B 512     // pack blocks per weight tensor

// ---------------- PTX helpers (all plain-sm_103 legal) -------------------------
__device__ __forceinline__ uint32_t smem_u32(const void* p) {
    uint32_t a;
    asm("{ .reg .u64 t; cvta.to.shared.u64 t, %1; cvt.u32.u64 %0, t; }" : "=r"(a) : "l"(p));
    return a;
}
#define LDSM4(r, a) \
    asm volatile("ldmatrix.sync.aligned.m8n8.x4.shared.b16 {%0,%1,%2,%3}, [%4];" \
        : "=r"((r)[0]), "=r"((r)[1]), "=r"((r)[2]), "=r"((r)[3]) : "r"(a))
#define MMA16816H(d, a, b0, b1) \
    asm volatile("mma.sync.aligned.m16n8k16.row.col.f32.f16.f16.f32 " \
        "{%0,%1,%2,%3}, {%4,%5,%6,%7}, {%8,%9}, {%0,%1,%2,%3};" \
        : "+f"((d)[0]), "+f"((d)[1]), "+f"((d)[2]), "+f"((d)[3]) \
        : "r"((a)[0]), "r"((a)[1]), "r"((a)[2]), "r"((a)[3]), "r"(b0), "r"(b1))
#define CP_ASYNC16(s, g, sz) \
    asm volatile("cp.async.cg.shared.global [%0], [%1], 16, %2;" :: "r"(s), "l"(g), "r"(sz))
#define CP_COMMIT() asm volatile("cp.async.commit_group;")
#define CP_WAIT0()  asm volatile("cp.async.wait_group 0;")
#define CP_WAIT1()  asm volatile("cp.async.wait_group 1;")

// ---------------- device scratch ----------------------------------------------
__device__ __align__(16) float   g_h[NN * HD];               // fp32 h (last layer only, for pool)
__device__ __align__(16) __half  g_h16[NN * HD];             // fp16 h (agg input)
__device__ __align__(16) __half  g_z16[NN * HD];             // fp16 z (GEMM1 A)
__device__ __align__(16) __half  g_u16[(size_t)NN * HD2];    // fp16 u (GEMM2 A)
__device__ __align__(16) __half  g_B1h[NL * HD2 * HD];       // [l][n=256][k=128] fp16
__device__ __align__(16) __half  g_B2h[NL * HD * HD2];       // [l][n=128][k=256] fp16
__device__ int g_deg[NN], g_rowptr[NN + 1], g_cursor[NN], g_col[NE];
__device__ int g_part[CSRB], g_poff[CSRB];
__device__ volatile int g_bar;                               // reset by k_pool

// ---------------- grid-wide barrier (296 co-resident CTAs, 2/SM) ----------------
__device__ __forceinline__ void gridbar(int phase) {
    __syncthreads();
    if (threadIdx.x == 0) {
        __threadfence();
        atomicAdd((int*)&g_bar, 1);
        while (g_bar < CSRB * phase) { }
        __threadfence();
    }
    __syncthreads();
}

// ---------------- fused CSR build (one launch, 296x512) ------------------------
__global__ void __launch_bounds__(CSRT, 2) k_csr(const int* __restrict__ ei) {
    const int tid = threadIdx.x, bid = blockIdx.x;
    const int gstride = CSRB * CSRT;
    const int gtid = bid * CSRT + tid;
    __shared__ int s[CSRT];

    for (int i = gtid; i < NN; i += gstride) g_deg[i] = 0;
    gridbar(1);
    for (int e = gtid; e < NE; e += gstride) atomicAdd(&g_deg[ei[NE + e]], 1);
    gridbar(2);
    const int start = bid * CHUNK;
    const int end = (start + CHUNK < NN) ? start + CHUNK : NN;
    const int i0 = start + tid;                    // one node per thread (338 < 512)
    int own = (i0 < end) ? g_deg[i0] : 0;
    s[tid] = own;
    __syncthreads();
    for (int off = 1; off < CSRT; off <<= 1) {
        int t = (tid >= off) ? s[tid - off] : 0;
        __syncthreads(); s[tid] += t; __syncthreads();
    }
    const int texcl = s[tid] - own;
    if (tid == CSRT - 1) g_part[bid] = s[tid];
    gridbar(3);
    if (bid == 0 && tid == 0) {
        int r = 0;
        for (int b = 0; b < CSRB; b++) { g_poff[b] = r; r += g_part[b]; }
    }
    gridbar(4);
    if (i0 < end) {
        int run = g_poff[bid] + texcl;
        g_rowptr[i0] = run;
        g_cursor[i0] = run;
    }
    if (gtid == 0) g_rowptr[NN] = NE;
    gridbar(5);
    for (int e = gtid; e < NE; e += gstride) {
        int p = atomicAdd(&g_cursor[ei[NE + e]], 1);
        g_col[p] = ei[e];
    }
}

// ---------------- fused embed + weight packing ----------------------------------
__global__ void k_embed_pack(const float* __restrict__ x, const float* __restrict__ Wemb,
                             const float* __restrict__ bemb,
                             const float* __restrict__ W1, const float* __restrict__ W2) {
    int bid = blockIdx.x;
    int tid = threadIdx.x;
    if (bid < EMB_B) {
        int idx = bid * 256 + tid;
        int n = idx >> 7, c = idx & 127;
        const float* xr = x + n * 9;
        float acc = bemb[c];
#pragma unroll
        for (int k = 0; k < 9; k++) acc = fmaf(xr[k], Wemb[k * HD + c], acc);
        g_h16[idx] = __float2half(acc);
    } else if (bid < EMB_B + PK_B) {
        int idx = (bid - EMB_B) * 256 + tid;        // NL*256*128
        int l = idx / (HD2 * HD), rem = idx % (HD2 * HD);
        int n = rem / HD, k = rem % HD;
        float w = W1[((size_t)l * HD + k) * HD2 + n];
        g_B1h[(size_t)l * HD2 * HD + (size_t)n * HD + k] = __float2half(w);
    } else {
        int idx = (bid - EMB_B - PK_B) * 256 + tid; // NL*128*256
        int l = idx / (HD * HD2), rem = idx % (HD * HD2);
        int n = rem / HD2, k = rem % HD2;
        float w = W2[((size_t)l * HD2 + k) * HD + n];
        g_B2h[(size_t)l * HD * HD2 + (size_t)n * HD2 + k] = __float2half(w);
    }
}

// ---------------- GIN aggregation: fp16 gather, fp32 accumulate -----------------
__global__ void k_agg(const float* __restrict__ eps, int l) {
    int node = (blockIdx.x * blockDim.x + threadIdx.x) >> 5;
    if (node >= NN) return;
    int lane = threadIdx.x & 31;
    const uint2* h16 = (const uint2*)g_h16;   // row = 32 uint2 (4 halves each)
    float sc = 1.0f + eps[l];
    uint2 sv = h16[(size_t)node * 32 + lane];
    float2 f0 = __half22float2(*(__half2*)&sv.x);
    float2 f1 = __half22float2(*(__half2*)&sv.y);
    float ax = f0.x * sc, ay = f0.y * sc, az = f1.x * sc, aw = f1.y * sc;
    int j = g_rowptr[node], e = g_rowptr[node + 1];
    for (; j + 3 < e; j += 4) {
        uint2 v0 = h16[(size_t)g_col[j]     * 32 + lane];
        uint2 v1 = h16[(size_t)g_col[j + 1] * 32 + lane];
        uint2 v2 = h16[(size_t)g_col[j + 2] * 32 + lane];
        uint2 v3 = h16[(size_t)g_col[j + 3] * 32 + lane];
        float2 f;
        f = __half22float2(*(__half2*)&v0.x); ax += f.x; ay += f.y;
        f = __half22float2(*(__half2*)&v0.y); az += f.x; aw += f.y;
        f = __half22float2(*(__half2*)&v1.x); ax += f.x; ay += f.y;
        f = __half22float2(*(__half2*)&v1.y); az += f.x; aw += f.y;
        f = __half22float2(*(__half2*)&v2.x); ax += f.x; ay += f.y;
        f = __half22float2(*(__half2*)&v2.y); az += f.x; aw += f.y;
        f = __half22float2(*(__half2*)&v3.x); ax += f.x; ay += f.y;
        f = __half22float2(*(__half2*)&v3.y); az += f.x; aw += f.y;
    }
    for (; j < e; j++) {
        uint2 v = h16[(size_t)g_col[j] * 32 + lane];
        float2 f;
        f = __half22float2(*(__half2*)&v.x); ax += f.x; ay += f.y;
        f = __half22float2(*(__half2*)&v.y); az += f.x; aw += f.y;
    }
    __half2 p0 = __floats2half2_rn(ax, ay);
    __half2 p1 = __floats2half2_rn(az, aw);
    uint2 ov = make_uint2(*(uint32_t*)&p0, *(uint32_t*)&p1);
    __stcs((uint2*)(g_z16 + (size_t)node * HD) + lane, ov);
}

// ---------------- HMMA GEMM + BN + ReLU (single-term fp16) ----------------------
// MODE 0: u16 = relu(BN(z @ W1)), KDIM=128, NOUT=256
// MODE 1: h16 (+h fp32 if last) = relu(BN(u @ W2)), KDIM=256, NOUT=128
// 256 threads, 2 CTAs/SM (independent barrier domains), 64-row tiles.
// 8 warps: wm = wid&1 (32 rows), wn = wid>>1 (NOUT/4 cols). Double-buffered A.
template <int KDIM, int NOUT, int MODE>
__global__ void __launch_bounds__(256, 2)
k_gemm_mma(int l, int last, const float* __restrict__ bb, const float* __restrict__ gm,
           const float* __restrict__ bt, const float* __restrict__ mn,
           const float* __restrict__ vr) {
    constexpr int PC  = 128 * 2 + 16;    // A chunk pitch (bytes)
    constexpr int PB  = KDIM * 2 + 16;   // B row pitch (bytes)
    constexpr int KT  = KDIM / 128;      // A k-chunks per tile
    constexpr int NT  = NOUT / 32;       // n8-tiles per warp
    constexpr int NW  = NOUT / 4;        // warp n-width
    constexpr int RCB = KDIM / 8;        // uint4 per B row
    constexpr int ACH = 64 * PC;         // A chunk bytes (64 rows)
    constexpr int BHI = 2 * ACH;
    constexpr int SAC = BHI + NOUT * PB;
    constexpr int SCC = SAC + NOUT * 4;

    extern __shared__ char smem[];
    const uint32_t sb = smem_u32(smem);
    const int tid = threadIdx.x, wid = tid >> 5, lane = tid & 31;
    const int wm = wid & 1, wn = wid >> 1;

    const __half* in = (MODE == 0) ? g_z16 : g_u16;
    const __half* Bsrc = (MODE == 0)
        ? (g_B1h + (size_t)l * HD2 * HD)
        : (g_B2h + (size_t)l * HD * HD2);

    for (int c = tid; c < NOUT * RCB; c += 256) {
        int n = c / RCB, q = c % RCB;
        const void* g = Bsrc + (size_t)c * 8;
        uint32_t s = sb + BHI + n * PB + q * 16;
        CP_ASYNC16(s, g, 16);
    }
    for (int c = tid; c < NOUT; c += 256) {
        float a = gm[c] * rsqrtf(vr[c] + 1e-5f);
        ((float*)(smem + SAC))[c] = a;
        ((float*)(smem + SCC))[c] = fmaf(a, bb[c] - mn[c], bt[c]);
    }
    CP_COMMIT();
    CP_WAIT0();
    __syncthreads();

    const float* Ac = (const float*)(smem + SAC);
    const float* Cc = (const float*)(smem + SCC);
    const uint32_t lrow = (lane & 15), lcol = (lane >> 4) * 16;
    const int tiles = (NN + 63) / 64;
    const int myTiles = (tiles > (int)blockIdx.x)
                        ? (tiles - blockIdx.x + gridDim.x - 1) / gridDim.x : 0;
    const int nchunks = myTiles * KT;

    auto issueA = [&](int chunk, int buf) {
        int tIdx = chunk / KT, kt = chunk % KT;
        int row0 = (blockIdx.x + tIdx * gridDim.x) * 64;
        for (int c = tid; c < 1024; c += 256) {
            int r = c >> 4, q = c & 15;
            int row = row0 + r;
            int ok = (row < NN);
            const void* g = in + (size_t)(ok ? row : 0) * KDIM + kt * 128 + q * 8;
            uint32_t s = sb + buf * ACH + r * PC + q * 16;
            CP_ASYNC16(s, g, ok ? 16 : 0);
        }
        CP_COMMIT();
    };

    float acc[2][NT][4];
#pragma unroll
    for (int i = 0; i < 2; i++)
#pragma unroll
        for (int j = 0; j < NT; j++)
#pragma unroll
            for (int q = 0; q < 4; q++) acc[i][j][q] = 0.f;

    if (nchunks > 0) issueA(0, 0);

    for (int ch = 0; ch < nchunks; ch++) {
        const int kt = ch % KT;
        const int tile = blockIdx.x + (ch / KT) * gridDim.x;
        const int buf = ch & 1;
        __syncthreads();     // all warps done reading buf (ch+1)&1 (race fix)
        if (ch + 1 < nchunks) { issueA(ch + 1, (ch + 1) & 1); CP_WAIT1(); }
        else                  { CP_WAIT0(); }
        __syncthreads();

#pragma unroll
        for (int ks = 0; ks < 8; ks++) {
            uint32_t ah[2][4];
#pragma unroll
            for (int i = 0; i < 2; i++) {
                uint32_t aAddr = sb + buf * ACH + (wm * 32 + i * 16 + lrow) * PC + ks * 32 + lcol;
                LDSM4(ah[i], aAddr);
            }
#pragma unroll
            for (int np = 0; np < NT / 2; np++) {
                int n0 = wn * NW + np * 16;
                uint32_t bAddr = sb + BHI + (n0 + lrow) * PB + (kt * 8 + ks) * 32 + lcol;
                uint32_t bh[4];
                LDSM4(bh, bAddr);
#pragma unroll
                for (int i = 0; i < 2; i++) {
                    MMA16816H(acc[i][2 * np],     ah[i], bh[0], bh[2]);
                    MMA16816H(acc[i][2 * np + 1], ah[i], bh[1], bh[3]);
                }
            }
        }

        if (kt == KT - 1) {
            const int row0 = tile * 64;
#pragma unroll
            for (int i = 0; i < 2; i++) {
#pragma unroll
                for (int j = 0; j < NT; j++) {
                    int r0 = row0 + wm * 32 + i * 16 + (lane >> 2);
                    int r1 = r0 + 8;
                    int c = wn * NW + j * 8 + (lane & 3) * 2;
                    float a0 = Ac[c], a1 = Ac[c + 1], c0 = Cc[c], c1 = Cc[c + 1];
                    float y00 = fmaxf(fmaf(acc[i][j][0], a0, c0), 0.f);
                    float y01 = fmaxf(fmaf(acc[i][j][1], a1, c1), 0.f);
                    float y10 = fmaxf(fmaf(acc[i][j][2], a0, c0), 0.f);
                    float y11 = fmaxf(fmaf(acc[i][j][3], a1, c1), 0.f);
                    if (MODE == 0) {
                        if (r0 < NN) {
                            __half2 p = __floats2half2_rn(y00, y01);
                            __stcs((uint32_t*)(g_u16 + (size_t)r0 * HD2 + c), *(uint32_t*)&p);
                        }
                        if (r1 < NN) {
                            __half2 p = __floats2half2_rn(y10, y11);
                            __stcs((uint32_t*)(g_u16 + (size_t)r1 * HD2 + c), *(uint32_t*)&p);
                        }
                    } else {
                        if (r0 < NN) {
                            __half2 p = __floats2half2_rn(y00, y01);
                            *(uint32_t*)(g_h16 + (size_t)r0 * HD + c) = *(uint32_t*)&p;
                            if (last) *(float2*)(g_h + (size_t)r0 * HD + c) = make_float2(y00, y01);
                        }
                        if (r1 < NN) {
                            __half2 p = __floats2half2_rn(y10, y11);
                            *(uint32_t*)(g_h16 + (size_t)r1 * HD + c) = *(uint32_t*)&p;
                            if (last) *(float2*)(g_h + (size_t)r1 * HD + c) = make_float2(y10, y11);
                        }
                    }
#pragma unroll
                    for (int q = 0; q < 4; q++) acc[i][j][q] = 0.f;
                }
            }
        }
    }
}

// ---------------- global mean pool (+ barrier reset for next replay) ----------
__global__ void k_pool(const int* __restrict__ batch, float* __restrict__ out) {
    if (blockIdx.x == 0 && threadIdx.x == 0) g_bar = 0;
    int g = blockIdx.x, c = threadIdx.x;
    int lo = 0, hi = NN;
    while (lo < hi) { int mid = (lo + hi) >> 1; if (batch[mid] < g) lo = mid + 1; else hi = mid; }
    int start = lo;
    lo = start; hi = NN;
    while (lo < hi) { int mid = (lo + hi) >> 1; if (batch[mid] < g + 1) lo = mid + 1; else hi = mid; }
    int end = lo;
    float acc = 0.f;
    int n = start;
    for (; n + 3 < end; n += 4) {
        acc += g_h[(n + 0) * HD + c];
        acc += g_h[(n + 1) * HD + c];
        acc += g_h[(n + 2) * HD + c];
        acc += g_h[(n + 3) * HD + c];
    }
    for (; n < end; n++) acc += g_h[n * HD + c];
    float cnt = (float)(end - start);
    out[g * HD + c] = acc / fmaxf(cnt, 1.f);
}

// ---------------- launch --------------------------------------------------------
extern "C" void kernel_launch(void* const* d_in, const int* in_sizes, int n_in,
                              void* d_out, int out_size) {
    const float* x    = (const float*)d_in[0];
    const int*   ei   = (const int*)d_in[1];
    const int*   bat  = (const int*)d_in[2];
    const float* Wemb = (const float*)d_in[3];
    const float* bemb = (const float*)d_in[4];
    const float* eps  = (const float*)d_in[5];
    const float* W1   = (const float*)d_in[6];
    const float* b1   = (const float*)d_in[7];
    const float* g1   = (const float*)d_in[8];
    const float* be1  = (const float*)d_in[9];
    const float* m1   = (const float*)d_in[10];
    const float* v1   = (const float*)d_in[11];
    const float* W2   = (const float*)d_in[12];
    const float* b2   = (const float*)d_in[13];
    const float* g2   = (const float*)d_in[14];
    const float* be2  = (const float*)d_in[15];
    const float* m2   = (const float*)d_in[16];
    const float* v2   = (const float*)d_in[17];
    float* out = (float*)d_out;

    // smem: MODE0 = 106496 B, MODE1 = 103424 B (2 CTAs/SM)
    cudaFuncSetAttribute(k_gemm_mma<128, 256, 0>, cudaFuncAttributeMaxDynamicSharedMemorySize, 106496);
    cudaFuncSetAttribute(k_gemm_mma<256, 128, 1>, cudaFuncAttributeMaxDynamicSharedMemorySize, 103424);

    // order: embed+pack(1), csr(2), agg(3), gemm1(4) -> ncu (launch #4) profiles gemm1
    k_embed_pack<<<EMB_B + 2 * PK_B, 256>>>(x, Wemb, bemb, W1, W2);  // 1
    k_csr<<<CSRB, CSRT>>>(ei);                                       // 2

    for (int l = 0; l < NL; l++) {
        k_agg<<<(NN + 7) / 8, 256>>>(eps, l);                        // 3 (l=0)
        k_gemm_mma<128, 256, 0><<<296, 256, 106496>>>(l, 0, b1 + l * HD2, g1 + l * HD2,
                                                      be1 + l * HD2, m1 + l * HD2, v1 + l * HD2);
        k_gemm_mma<256, 128, 1><<<296, 256, 103424>>>(l, (l == NL - 1) ? 1 : 0,
                                                      b2 + l * HD, g2 + l * HD,
                                                      be2 + l * HD, m2 + l * HD, v2 + l * HD);
    }

    k_pool<<<NG, 128>>>(bat, out);
}

// round 12
// speedup vs baseline: 1.9789x; 1.0358x over previous
#include <cuda_runtime.h>
#include <cuda_fp16.h>
#include <cstdint>

#define NN 100000
#define NE 3200000
#define HD 128
#define HD2 256
#define NL 4
#define NG 512
#define CSRB 296
#define CSRT 512
#define CHUNK 338    // ceil(NN/296)
#define EMB_B 50000  // embed blocks (NN*HD/256)
#define PK_B 512     // pack blocks per weight tensor

// ---------------- PTX helpers (all plain-sm_103 legal) -------------------------
__device__ __forceinline__ uint32_t smem_u32(const void* p) {
    uint32_t a;
    asm("{ .reg .u64 t; cvta.to.shared.u64 t, %1; cvt.u32.u64 %0, t; }" : "=r"(a) : "l"(p));
    return a;
}
#define LDSM4(r, a) \
    asm volatile("ldmatrix.sync.aligned.m8n8.x4.shared.b16 {%0,%1,%2,%3}, [%4];" \
        : "=r"((r)[0]), "=r"((r)[1]), "=r"((r)[2]), "=r"((r)[3]) : "r"(a))
#define MMA16816H(d, a, b0, b1) \
    asm volatile("mma.sync.aligned.m16n8k16.row.col.f32.f16.f16.f32 " \
        "{%0,%1,%2,%3}, {%4,%5,%6,%7}, {%8,%9}, {%0,%1,%2,%3};" \
        : "+f"((d)[0]), "+f"((d)[1]), "+f"((d)[2]), "+f"((d)[3]) \
        : "r"((a)[0]), "r"((a)[1]), "r"((a)[2]), "r"((a)[3]), "r"(b0), "r"(b1))
#define CP_ASYNC16(s, g, sz) \
    asm volatile("cp.async.cg.shared.global [%0], [%1], 16, %2;" :: "r"(s), "l"(g), "r"(sz))
#define CP_COMMIT() asm volatile("cp.async.commit_group;")
#define CP_WAIT0()  asm volatile("cp.async.wait_group 0;")
#define CP_WAIT1()  asm volatile("cp.async.wait_group 1;")

// ---------------- device scratch ----------------------------------------------
__device__ __align__(16) float   g_h[NN * HD];               // fp32 h (last layer only, for pool)
__device__ __align__(16) __half  g_h16[NN * HD];             // fp16 h (agg input)
__device__ __align__(16) __half  g_z16[NN * HD];             // fp16 z (GEMM1 A)
__device__ __align__(16) __half  g_u16[(size_t)NN * HD2];    // fp16 u (GEMM2 A)
__device__ __align__(16) __half  g_B1h[NL * HD2 * HD];       // [l][n=256][k=128] fp16
__device__ __align__(16) __half  g_B2h[NL * HD * HD2];       // [l][n=128][k=256] fp16
__device__ int g_deg[NN], g_rowptr[NN + 1], g_cursor[NN], g_col[NE];
__device__ int g_part[CSRB], g_poff[CSRB];
__device__ volatile int g_bar;                               // reset by k_pool

// ---------------- grid-wide barrier (296 co-resident CTAs, 2/SM) ----------------
__device__ __forceinline__ void gridbar(int phase) {
    __syncthreads();
    if (threadIdx.x == 0) {
        __threadfence();
        atomicAdd((int*)&g_bar, 1);
        while (g_bar < CSRB * phase) { }
        __threadfence();
    }
    __syncthreads();
}

// ---------------- fused CSR build (one launch, 296x512) ------------------------
__global__ void __launch_bounds__(CSRT, 2) k_csr(const int* __restrict__ ei) {
    const int tid = threadIdx.x, bid = blockIdx.x;
    const int gstride = CSRB * CSRT;
    const int gtid = bid * CSRT + tid;
    __shared__ int s[CSRT];

    for (int i = gtid; i < NN; i += gstride) g_deg[i] = 0;
    gridbar(1);
    for (int e = gtid; e < NE; e += gstride) atomicAdd(&g_deg[ei[NE + e]], 1);
    gridbar(2);
    const int start = bid * CHUNK;
    const int end = (start + CHUNK < NN) ? start + CHUNK : NN;
    const int i0 = start + tid;                    // one node per thread (338 < 512)
    int own = (i0 < end) ? g_deg[i0] : 0;
    s[tid] = own;
    __syncthreads();
    for (int off = 1; off < CSRT; off <<= 1) {
        int t = (tid >= off) ? s[tid - off] : 0;
        __syncthreads(); s[tid] += t; __syncthreads();
    }
    const int texcl = s[tid] - own;
    if (tid == CSRT - 1) g_part[bid] = s[tid];
    gridbar(3);
    if (bid == 0 && tid == 0) {
        int r = 0;
        for (int b = 0; b < CSRB; b++) { g_poff[b] = r; r += g_part[b]; }
    }
    gridbar(4);
    if (i0 < end) {
        int run = g_poff[bid] + texcl;
        g_rowptr[i0] = run;
        g_cursor[i0] = run;
    }
    if (gtid == 0) g_rowptr[NN] = NE;
    gridbar(5);
    for (int e = gtid; e < NE; e += gstride) {
        int p = atomicAdd(&g_cursor[ei[NE + e]], 1);
        g_col[p] = ei[e];
    }
}

// ---------------- fused embed + weight packing ----------------------------------
__global__ void k_embed_pack(const float* __restrict__ x, const float* __restrict__ Wemb,
                             const float* __restrict__ bemb,
                             const float* __restrict__ W1, const float* __restrict__ W2) {
    int bid = blockIdx.x;
    int tid = threadIdx.x;
    if (bid < EMB_B) {
        int idx = bid * 256 + tid;
        int n = idx >> 7, c = idx & 127;
        const float* xr = x + n * 9;
        float acc = bemb[c];
#pragma unroll
        for (int k = 0; k < 9; k++) acc = fmaf(xr[k], Wemb[k * HD + c], acc);
        g_h16[idx] = __float2half(acc);
    } else if (bid < EMB_B + PK_B) {
        int idx = (bid - EMB_B) * 256 + tid;        // NL*256*128
        int l = idx / (HD2 * HD), rem = idx % (HD2 * HD);
        int n = rem / HD, k = rem % HD;
        float w = W1[((size_t)l * HD + k) * HD2 + n];
        g_B1h[(size_t)l * HD2 * HD + (size_t)n * HD + k] = __float2half(w);
    } else {
        int idx = (bid - EMB_B - PK_B) * 256 + tid; // NL*128*256
        int l = idx / (HD * HD2), rem = idx % (HD * HD2);
        int n = rem / HD2, k = rem % HD2;
        float w = W2[((size_t)l * HD2 + k) * HD + n];
        g_B2h[(size_t)l * HD * HD2 + (size_t)n * HD2 + k] = __float2half(w);
    }
}

// ---------------- GIN aggregation: fp16 gather, fp32 accumulate -----------------
__global__ void k_agg(const float* __restrict__ eps, int l) {
    int node = (blockIdx.x * blockDim.x + threadIdx.x) >> 5;
    if (node >= NN) return;
    int lane = threadIdx.x & 31;
    const uint2* h16 = (const uint2*)g_h16;   // row = 32 uint2 (4 halves each)
    float sc = 1.0f + eps[l];
    uint2 sv = h16[(size_t)node * 32 + lane];
    float2 f0 = __half22float2(*(__half2*)&sv.x);
    float2 f1 = __half22float2(*(__half2*)&sv.y);
    float ax = f0.x * sc, ay = f0.y * sc, az = f1.x * sc, aw = f1.y * sc;
    int j = g_rowptr[node], e = g_rowptr[node + 1];
    for (; j + 3 < e; j += 4) {
        uint2 v0 = h16[(size_t)g_col[j]     * 32 + lane];
        uint2 v1 = h16[(size_t)g_col[j + 1] * 32 + lane];
        uint2 v2 = h16[(size_t)g_col[j + 2] * 32 + lane];
        uint2 v3 = h16[(size_t)g_col[j + 3] * 32 + lane];
        float2 f;
        f = __half22float2(*(__half2*)&v0.x); ax += f.x; ay += f.y;
        f = __half22float2(*(__half2*)&v0.y); az += f.x; aw += f.y;
        f = __half22float2(*(__half2*)&v1.x); ax += f.x; ay += f.y;
        f = __half22float2(*(__half2*)&v1.y); az += f.x; aw += f.y;
        f = __half22float2(*(__half2*)&v2.x); ax += f.x; ay += f.y;
        f = __half22float2(*(__half2*)&v2.y); az += f.x; aw += f.y;
        f = __half22float2(*(__half2*)&v3.x); ax += f.x; ay += f.y;
        f = __half22float2(*(__half2*)&v3.y); az += f.x; aw += f.y;
    }
    for (; j < e; j++) {
        uint2 v = h16[(size_t)g_col[j] * 32 + lane];
        float2 f;
        f = __half22float2(*(__half2*)&v.x); ax += f.x; ay += f.y;
        f = __half22float2(*(__half2*)&v.y); az += f.x; aw += f.y;
    }
    __half2 p0 = __floats2half2_rn(ax, ay);
    __half2 p1 = __floats2half2_rn(az, aw);
    uint2 ov = make_uint2(*(uint32_t*)&p0, *(uint32_t*)&p1);
    __stcs((uint2*)(g_z16 + (size_t)node * HD) + lane, ov);
}

// ---------------- HMMA GEMM + BN + ReLU (fp16, B fragments in registers) --------
// MODE 0: u16 = relu(BN(z @ W1)), KDIM=128, NOUT=256
// MODE 1: h16 (+h fp32 if last) = relu(BN(u @ W2)), KDIM=256, NOUT=128
// 148 persistent CTAs x 256 threads (1/SM). Warp grid 2x4: wm=32 rows, wn=NOUT/4.
// Per-warp B slice (16KB = 128 regs/lane) hoisted to registers once; mainloop
// does only A-LDSM. A tiles (64 rows x full K) double-buffered via cp.async.
template <int KDIM, int NOUT, int MODE>
__global__ void __launch_bounds__(256, 1)
k_gemm_mma(int l, int last, const float* __restrict__ bb, const float* __restrict__ gm,
           const float* __restrict__ bt, const float* __restrict__ mn,
           const float* __restrict__ vr) {
    constexpr int PC  = KDIM * 2 + 16;   // A row pitch (bytes)
    constexpr int PB  = KDIM * 2 + 16;   // B row pitch (bytes)
    constexpr int KS  = KDIM / 16;       // k16 steps
    constexpr int NT  = NOUT / 32;       // n8-tiles per warp
    constexpr int NW  = NOUT / 4;        // warp n-width
    constexpr int RCA = KDIM / 8;        // uint4 per A row
    constexpr int ACH = 64 * PC;         // A buffer bytes (64 rows, full K)
    constexpr int BHI = 2 * ACH;
    constexpr int SAC = BHI + NOUT * PB;
    constexpr int SCC = SAC + NOUT * 4;

    extern __shared__ char smem[];
    const uint32_t sb = smem_u32(smem);
    const int tid = threadIdx.x, wid = tid >> 5, lane = tid & 31;
    const int wm = wid & 1, wn = wid >> 1;

    const __half* in = (MODE == 0) ? g_z16 : g_u16;
    const __half* Bsrc = (MODE == 0)
        ? (g_B1h + (size_t)l * HD2 * HD)
        : (g_B2h + (size_t)l * HD * HD2);

    // stage B + BN constants
    for (int c = tid; c < NOUT * RCA; c += 256) {
        int n = c / RCA, q = c % RCA;
        const void* g = Bsrc + (size_t)c * 8;
        uint32_t s = sb + BHI + n * PB + q * 16;
        CP_ASYNC16(s, g, 16);
    }
    for (int c = tid; c < NOUT; c += 256) {
        float a = gm[c] * rsqrtf(vr[c] + 1e-5f);
        ((float*)(smem + SAC))[c] = a;
        ((float*)(smem + SCC))[c] = fmaf(a, bb[c] - mn[c], bt[c]);
    }
    CP_COMMIT();
    CP_WAIT0();
    __syncthreads();

    const float* Ac = (const float*)(smem + SAC);
    const float* Cc = (const float*)(smem + SCC);
    const uint32_t lrow = (lane & 15), lcol = (lane >> 4) * 16;

    // hoist this warp's B slice into registers (tile-invariant)
    uint32_t bfr[KS][NT / 2][4];
#pragma unroll
    for (int ks = 0; ks < KS; ks++)
#pragma unroll
        for (int np = 0; np < NT / 2; np++) {
            uint32_t bAddr = sb + BHI + (wn * NW + np * 16 + lrow) * PB + ks * 32 + lcol;
            LDSM4(bfr[ks][np], bAddr);
        }

    const int tiles = (NN + 63) / 64;
    const int myTiles = (tiles > (int)blockIdx.x)
                        ? (tiles - blockIdx.x + gridDim.x - 1) / gridDim.x : 0;

    auto issueA = [&](int t, int buf) {
        int row0 = (blockIdx.x + t * gridDim.x) * 64;
        for (int c = tid; c < 64 * RCA; c += 256) {
            int r = c / RCA, q = c % RCA;
            int row = row0 + r;
            int ok = (row < NN);
            const void* g = in + (size_t)(ok ? row : 0) * KDIM + q * 8;
            uint32_t s = sb + buf * ACH + r * PC + q * 16;
            CP_ASYNC16(s, g, ok ? 16 : 0);
        }
        CP_COMMIT();
    };

    if (myTiles > 0) issueA(0, 0);

    for (int t = 0; t < myTiles; t++) {
        const int buf = t & 1;
        const int row0 = (blockIdx.x + t * gridDim.x) * 64;
        __syncthreads();     // all warps done reading buf (t+1)&1 from iter t-1
        if (t + 1 < myTiles) { issueA(t + 1, (t + 1) & 1); CP_WAIT1(); }
        else                 { CP_WAIT0(); }
        __syncthreads();

        float acc[2][NT][4];
#pragma unroll
        for (int i = 0; i < 2; i++)
#pragma unroll
            for (int j = 0; j < NT; j++)
#pragma unroll
                for (int q = 0; q < 4; q++) acc[i][j][q] = 0.f;

#pragma unroll
        for (int ks = 0; ks < KS; ks++) {
            uint32_t ah[2][4];
#pragma unroll
            for (int i = 0; i < 2; i++) {
                uint32_t aAddr = sb + buf * ACH + (wm * 32 + i * 16 + lrow) * PC + ks * 32 + lcol;
                LDSM4(ah[i], aAddr);
            }
#pragma unroll
            for (int np = 0; np < NT / 2; np++) {
#pragma unroll
                for (int i = 0; i < 2; i++) {
                    MMA16816H(acc[i][2 * np],     ah[i], bfr[ks][np][0], bfr[ks][np][2]);
                    MMA16816H(acc[i][2 * np + 1], ah[i], bfr[ks][np][1], bfr[ks][np][3]);
                }
            }
        }

        // epilogue: BN + ReLU
#pragma unroll
        for (int i = 0; i < 2; i++) {
#pragma unroll
            for (int j = 0; j < NT; j++) {
                int r0 = row0 + wm * 32 + i * 16 + (lane >> 2);
                int r1 = r0 + 8;
                int c = wn * NW + j * 8 + (lane & 3) * 2;
                float a0 = Ac[c], a1 = Ac[c + 1], c0 = Cc[c], c1 = Cc[c + 1];
                float y00 = fmaxf(fmaf(acc[i][j][0], a0, c0), 0.f);
                float y01 = fmaxf(fmaf(acc[i][j][1], a1, c1), 0.f);
                float y10 = fmaxf(fmaf(acc[i][j][2], a0, c0), 0.f);
                float y11 = fmaxf(fmaf(acc[i][j][3], a1, c1), 0.f);
                if (MODE == 0) {
                    if (r0 < NN) {
                        __half2 p = __floats2half2_rn(y00, y01);
                        __stcs((uint32_t*)(g_u16 + (size_t)r0 * HD2 + c), *(uint32_t*)&p);
                    }
                    if (r1 < NN) {
                        __half2 p = __floats2half2_rn(y10, y11);
                        __stcs((uint32_t*)(g_u16 + (size_t)r1 * HD2 + c), *(uint32_t*)&p);
                    }
                } else {
                    if (r0 < NN) {
                        __half2 p = __floats2half2_rn(y00, y01);
                        *(uint32_t*)(g_h16 + (size_t)r0 * HD + c) = *(uint32_t*)&p;
                        if (last) *(float2*)(g_h + (size_t)r0 * HD + c) = make_float2(y00, y01);
                    }
                    if (r1 < NN) {
                        __half2 p = __floats2half2_rn(y10, y11);
                        *(uint32_t*)(g_h16 + (size_t)r1 * HD + c) = *(uint32_t*)&p;
                        if (last) *(float2*)(g_h + (size_t)r1 * HD + c) = make_float2(y10, y11);
                    }
                }
            }
        }
    }
}

// ---------------- global mean pool (+ barrier reset for next replay) ----------
__global__ void k_pool(const int* __restrict__ batch, float* __restrict__ out) {
    if (blockIdx.x == 0 && threadIdx.x == 0) g_bar = 0;
    int g = blockIdx.x, c = threadIdx.x;
    int lo = 0, hi = NN;
    while (lo < hi) { int mid = (lo + hi) >> 1; if (batch[mid] < g) lo = mid + 1; else hi = mid; }
    int start = lo;
    lo = start; hi = NN;
    while (lo < hi) { int mid = (lo + hi) >> 1; if (batch[mid] < g + 1) lo = mid + 1; else hi = mid; }
    int end = lo;
    float acc = 0.f;
    int n = start;
    for (; n + 3 < end; n += 4) {
        acc += g_h[(n + 0) * HD + c];
        acc += g_h[(n + 1) * HD + c];
        acc += g_h[(n + 2) * HD + c];
        acc += g_h[(n + 3) * HD + c];
    }
    for (; n < end; n++) acc += g_h[n * HD + c];
    float cnt = (float)(end - start);
    out[g * HD + c] = acc / fmaxf(cnt, 1.f);
}

// ---------------- launch --------------------------------------------------------
extern "C" void kernel_launch(void* const* d_in, const int* in_sizes, int n_in,
                              void* d_out, int out_size) {
    const float* x    = (const float*)d_in[0];
    const int*   ei   = (const int*)d_in[1];
    const int*   bat  = (const int*)d_in[2];
    const float* Wemb = (const float*)d_in[3];
    const float* bemb = (const float*)d_in[4];
    const float* eps  = (const float*)d_in[5];
    const float* W1   = (const float*)d_in[6];
    const float* b1   = (const float*)d_in[7];
    const float* g1   = (const float*)d_in[8];
    const float* be1  = (const float*)d_in[9];
    const float* m1   = (const float*)d_in[10];
    const float* v1   = (const float*)d_in[11];
    const float* W2   = (const float*)d_in[12];
    const float* b2   = (const float*)d_in[13];
    const float* g2   = (const float*)d_in[14];
    const float* be2  = (const float*)d_in[15];
    const float* m2   = (const float*)d_in[16];
    const float* v2   = (const float*)d_in[17];
    float* out = (float*)d_out;

    // smem: MODE0 = 106496 B, MODE1 = 136192 B (1 CTA/SM)
    cudaFuncSetAttribute(k_gemm_mma<128, 256, 0>, cudaFuncAttributeMaxDynamicSharedMemorySize, 106496);
    cudaFuncSetAttribute(k_gemm_mma<256, 128, 1>, cudaFuncAttributeMaxDynamicSharedMemorySize, 136192);

    // order: embed+pack(1), csr(2), agg(3), gemm1(4) -> ncu (launch #4) profiles gemm1
    k_embed_pack<<<EMB_B + 2 * PK_B, 256>>>(x, Wemb, bemb, W1, W2);  // 1
    k_csr<<<CSRB, CSRT>>>(ei);                                       // 2

    for (int l = 0; l < NL; l++) {
        k_agg<<<(NN + 7) / 8, 256>>>(eps, l);                        // 3 (l=0)
        k_gemm_mma<128, 256, 0><<<148, 256, 106496>>>(l, 0, b1 + l * HD2, g1 + l * HD2,
                                                      be1 + l * HD2, m1 + l * HD2, v1 + l * HD2);
        k_gemm_mma<256, 128, 1><<<148, 256, 136192>>>(l, (l == NL - 1) ? 1 : 0,
                                                      b2 + l * HD, g2 + l * HD,
                                                      be2 + l * HD, m2 + l * HD, v2 + l * HD);
    }

    k_pool<<<NG, 128>>>(bat, out);
}